// round 7
// baseline (speedup 1.0000x reference)
#include <cuda_runtime.h>
#include <math.h>
#include <stdint.h>

#define SEQ 2048
#define DIM 1280
#define NH  16
#define HD  80

// Scratch (device globals)
__device__ float g_Q[SEQ * DIM];
__device__ float g_K[SEQ * DIM];
__device__ float g_Vt[SEQ * DIM];    // V transposed: [DIM][SEQ], tf32-rounded
__device__ float g_A[SEQ * DIM];
__device__ float g_Xr[SEQ * DIM];    // tf32-rounded hidden_states
__device__ float g_Wqr[DIM * DIM];
__device__ float g_Wkr[DIM * DIM];
__device__ float g_Wvr[DIM * DIM];
__device__ float g_Wor[DIM * DIM];

__device__ __forceinline__ float f2tf32(float x) {
    uint32_t u;
    asm("cvt.rna.tf32.f32 %0, %1;" : "=r"(u) : "f"(x));
    return __uint_as_float(u);
}

__device__ __forceinline__ void mma_tf32(float* c, const uint32_t* a, const uint32_t* b) {
    asm("mma.sync.aligned.m16n8k8.row.col.f32.tf32.tf32.f32 "
        "{%0,%1,%2,%3}, {%4,%5,%6,%7}, {%8,%9}, {%0,%1,%2,%3};"
        : "+f"(c[0]), "+f"(c[1]), "+f"(c[2]), "+f"(c[3])
        : "r"(a[0]), "r"(a[1]), "r"(a[2]), "r"(a[3]), "r"(b[0]), "r"(b[1]));
}

__device__ __forceinline__ void cp16(uint32_t dst, const void* src) {
    asm volatile("cp.async.cg.shared.global [%0], [%1], 16;\n" :: "r"(dst), "l"(src));
}
__device__ __forceinline__ void cp16z(uint32_t dst, const void* src, int bytes) {
    asm volatile("cp.async.cg.shared.global [%0], [%1], 16, %2;\n"
                 :: "r"(dst), "l"(src), "r"(bytes));
}

// ---------------------------------------------------------------------------
// Fused tf32 rounding for X + all 4 weights (one launch).
// ---------------------------------------------------------------------------
#define NX4 (SEQ * DIM / 4)
#define NW4 (DIM * DIM / 4)
__global__ void cvt_all(const float* __restrict__ X,
                        const float* __restrict__ Wq, const float* __restrict__ Wk,
                        const float* __restrict__ Wv, const float* __restrict__ Wo)
{
    int i = blockIdx.x * blockDim.x + threadIdx.x;
    const float* src; float* dst; int off;
    if (i < NX4)               { src = X;  dst = g_Xr;  off = i; }
    else if (i < NX4 + NW4)    { src = Wq; dst = g_Wqr; off = i - NX4; }
    else if (i < NX4 + 2*NW4)  { src = Wk; dst = g_Wkr; off = i - NX4 - NW4; }
    else if (i < NX4 + 3*NW4)  { src = Wv; dst = g_Wvr; off = i - NX4 - 2*NW4; }
    else if (i < NX4 + 4*NW4)  { src = Wo; dst = g_Wor; off = i - NX4 - 3*NW4; }
    else return;
    float4 v = ((const float4*)src)[off];
    ((float4*)dst)[off] = make_float4(f2tf32(v.x), f2tf32(v.y), f2tf32(v.z), f2tf32(v.w));
}

// ---------------------------------------------------------------------------
// TF32 GEMM (NT), 2-stage cp.async pipeline, balanced grid (128 CTAs).
// 512 threads = 16 warps in a 4x4 grid; warp tile 32x40 (acc 2x5x4 = 40 regs).
// 4 warps per SMSP for latency hiding (was 2).
// TRANS epilogue also rounds output to tf32 (feeds attention V operand).
// ---------------------------------------------------------------------------
#define BM 128
#define BN 160
#define BK 32
#define SST 36
#define GEMM_SMEM ((2 * BM * SST + 2 * BN * SST) * 4)   // 82944 B

template<bool TRANS>
__global__ __launch_bounds__(512, 1)
void gemm_tf32_pipe(const float* __restrict__ A, const float* __restrict__ B,
                    const float* __restrict__ bias, float* __restrict__ C,
                    int M, int N, int K)
{
    extern __shared__ float sm[];
    float* As = sm;                    // [2][BM*SST]
    float* Bs = sm + 2 * BM * SST;     // [2][BN*SST]

    const int tid = threadIdx.x;
    const int m0 = blockIdx.y * BM;
    const int n0 = blockIdx.x * BN;

    const int warp = tid >> 5, lane = tid & 31;
    const int wm = warp >> 2, wn = warp & 3;     // 4 x 4 warps
    const int g = lane >> 2, tg = lane & 3;

    const uint32_t sA = (uint32_t)__cvta_generic_to_shared(As);
    const uint32_t sB = (uint32_t)__cvta_generic_to_shared(Bs);

    float acc[2][5][4];
#pragma unroll
    for (int mt = 0; mt < 2; mt++)
#pragma unroll
        for (int nt = 0; nt < 5; nt++)
#pragma unroll
            for (int r = 0; r < 4; r++) acc[mt][nt][r] = 0.f;

    const int T = K / BK;   // 40

    auto issue = [&](int stage, int kt) {
        // A: 128 rows x 32 k = 1024 chunks; 512 threads -> 2 iters
#pragma unroll
        for (int t = 0; t < 2; t++) {
            int idx = tid + t * 512;
            int r = idx >> 3;
            int kc = (idx & 7) << 2;
            uint32_t off = (uint32_t)(stage * BM * SST + r * SST + kc) * 4u;
            cp16(sA + off, A + (size_t)(m0 + r) * K + kt + kc);
        }
        // B: 160 rows x 32 k = 1280 chunks; 2 full iters + 256 extra
#pragma unroll
        for (int t = 0; t < 2; t++) {
            int idx = tid + t * 512;
            int r = idx >> 3;
            int kc = (idx & 7) << 2;
            uint32_t off = (uint32_t)(stage * BN * SST + r * SST + kc) * 4u;
            cp16(sB + off, B + (size_t)(n0 + r) * K + kt + kc);
        }
        if (tid < 256) {
            int idx = tid + 1024;
            int r = idx >> 3;
            int kc = (idx & 7) << 2;
            uint32_t off = (uint32_t)(stage * BN * SST + r * SST + kc) * 4u;
            cp16(sB + off, B + (size_t)(n0 + r) * K + kt + kc);
        }
        asm volatile("cp.async.commit_group;\n");
    };

    issue(0, 0);

    for (int ti = 0; ti < T; ti++) {
        if (ti + 1 < T) {
            issue((ti + 1) & 1, (ti + 1) * BK);
            asm volatile("cp.async.wait_group 1;\n");
        } else {
            asm volatile("cp.async.wait_group 0;\n");
        }
        __syncthreads();

        const float* Asr = As + (ti & 1) * BM * SST;
        const float* Bsr = Bs + (ti & 1) * BN * SST;

#pragma unroll
        for (int ks = 0; ks < 4; ks++) {
            const int k0 = ks * 8;
            uint32_t af[2][4], bf[5][2];
#pragma unroll
            for (int mt = 0; mt < 2; mt++) {
                int r = wm * 32 + mt * 16 + g;
                af[mt][0] = __float_as_uint(Asr[r * SST + k0 + tg]);
                af[mt][1] = __float_as_uint(Asr[(r + 8) * SST + k0 + tg]);
                af[mt][2] = __float_as_uint(Asr[r * SST + k0 + tg + 4]);
                af[mt][3] = __float_as_uint(Asr[(r + 8) * SST + k0 + tg + 4]);
            }
#pragma unroll
            for (int nt = 0; nt < 5; nt++) {
                int c = wn * 40 + nt * 8 + g;
                bf[nt][0] = __float_as_uint(Bsr[c * SST + k0 + tg]);
                bf[nt][1] = __float_as_uint(Bsr[c * SST + k0 + tg + 4]);
            }
#pragma unroll
            for (int mt = 0; mt < 2; mt++)
#pragma unroll
                for (int nt = 0; nt < 5; nt++)
                    mma_tf32(acc[mt][nt], af[mt], bf[nt]);
        }
        __syncthreads();
    }

#pragma unroll
    for (int mt = 0; mt < 2; mt++) {
#pragma unroll
        for (int nt = 0; nt < 5; nt++) {
            int r = m0 + wm * 32 + mt * 16 + g;
            int c = n0 + wn * 40 + nt * 8 + 2 * tg;
            float2 bb = *(const float2*)(bias + c);
            if (!TRANS) {
                float2 v0 = make_float2(acc[mt][nt][0] + bb.x, acc[mt][nt][1] + bb.y);
                float2 v1 = make_float2(acc[mt][nt][2] + bb.x, acc[mt][nt][3] + bb.y);
                *(float2*)(C + (size_t)r * N + c) = v0;
                *(float2*)(C + (size_t)(r + 8) * N + c) = v1;
            } else {
                C[(size_t)c * M + r]           = f2tf32(acc[mt][nt][0] + bb.x);
                C[(size_t)(c + 1) * M + r]     = f2tf32(acc[mt][nt][1] + bb.y);
                C[(size_t)c * M + r + 8]       = f2tf32(acc[mt][nt][2] + bb.x);
                C[(size_t)(c + 1) * M + r + 8] = f2tf32(acc[mt][nt][3] + bb.y);
            }
        }
    }
}

// ---------------------------------------------------------------------------
// RoPE in place on g_Q / g_K. Q additionally pre-scaled by 1/sqrt(hd).
// Both outputs tf32-rounded so attention fills are pure copies.
// ---------------------------------------------------------------------------
__global__ void rope_kernel(const float* __restrict__ cs, const float* __restrict__ sn)
{
    int idx = blockIdx.x * blockDim.x + threadIdx.x;
    const int total = SEQ * NH * (HD / 2);
    if (idx >= total) return;
    int j = idx % (HD / 2);
    int h = (idx / (HD / 2)) % NH;
    int s = idx / ((HD / 2) * NH);
    int base = s * DIM + h * HD;
    const float scale = rsqrtf((float)HD);
    float c0 = cs[s * HD + j],      s0 = sn[s * HD + j];
    float c1 = cs[s * HD + j + 40], s1 = sn[s * HD + j + 40];
    {
        float x0 = g_Q[base + j], x1 = g_Q[base + j + 40];
        g_Q[base + j]      = f2tf32((x0 * c0 - x1 * s0) * scale);
        g_Q[base + j + 40] = f2tf32((x1 * c1 + x0 * s1) * scale);
    }
    {
        float x0 = g_K[base + j], x1 = g_K[base + j + 40];
        g_K[base + j]      = f2tf32(x0 * c0 - x1 * s0);
        g_K[base + j + 40] = f2tf32(x1 * c1 + x0 * s1);
    }
}

// ---------------------------------------------------------------------------
// Persistent segmented flash attention, tf32 mma, cp.async-pipelined fills.
// grid = 296 (148 SM x occ 2), 128 thr. V_i loads during S_i; K_{i+1} loads
// during softmax+PV_i. All inputs pre-rounded -> fills are raw 16B copies.
// ---------------------------------------------------------------------------
#define ATT_GRID 296
#define QS_STR 84
#define VT_STR 68
#define AT_KS  (64 * QS_STR)
#define AT_VT  (2 * 64 * QS_STR)
#define AT_PS  (AT_VT + 80 * VT_STR)
#define ATTN_SMEM ((AT_PS + 64 * VT_STR) * 4)   // 82176 B

__global__ __launch_bounds__(128)
void attn_mma(const int* __restrict__ cu, float* __restrict__ out)
{
    extern __shared__ float sm[];
    float* Qs = sm;
    float* Ks = sm + AT_KS;
    float* Vt = sm + AT_VT;
    float* Ps = sm + AT_PS;

    const uint32_t sQ = (uint32_t)__cvta_generic_to_shared(Qs);
    const uint32_t sK = (uint32_t)__cvta_generic_to_shared(Ks);
    const uint32_t sV = (uint32_t)__cvta_generic_to_shared(Vt);

    const int tid = threadIdx.x;
    const int warp = tid >> 5, lane = tid & 31;
    const int g = lane >> 2, tg = lane & 3;
    const int m0 = warp * 16;

    for (int item = blockIdx.x; item < (SEQ / 64) * NH; item += ATT_GRID) {
        const int qb = (item >> 4) * 64;
        const int h  = item & 15;

        int ks = 0, ke = SEQ;
#pragma unroll
        for (int i = 0; i < 4; i++)
            if (qb >= cu[i] && qb < cu[i + 1]) { ks = cu[i]; ke = cu[i + 1]; }

        __syncthreads();   // prior item's smem readers done

        // Q fill (group) + first K fill (group)
#pragma unroll
        for (int t = 0; t < 10; t++) {
            int idx = tid + t * 128;
            int r = idx / 20, dc = (idx % 20) * 4;
            cp16(sQ + (uint32_t)(r * QS_STR + dc) * 4u,
                 g_Q + (size_t)(qb + r) * DIM + h * HD + dc);
        }
        asm volatile("cp.async.commit_group;\n");
        {
            int kn0 = min(64, ke - ks);
#pragma unroll
            for (int t = 0; t < 10; t++) {
                int idx = tid + t * 128;
                int r = idx / 20, dc = (idx % 20) * 4;
                int srow = (r < kn0) ? (ks + r) : ks;
                cp16z(sK + (uint32_t)(r * QS_STR + dc) * 4u,
                      g_K + (size_t)srow * DIM + h * HD + dc, (r < kn0) ? 16 : 0);
            }
            asm volatile("cp.async.commit_group;\n");
        }

        float mrow[2] = {-1e30f, -1e30f};
        float lrow[2] = {0.f, 0.f};
        float o[10][4];
#pragma unroll
        for (int nt = 0; nt < 10; nt++)
#pragma unroll
            for (int r = 0; r < 4; r++) o[nt][r] = 0.f;

        for (int kt = ks; kt < ke; kt += 64) {
            int kn = min(64, ke - kt);
            asm volatile("cp.async.wait_group 0;\n");
            __syncthreads();

            // Issue V_kt (overlaps S compute)
#pragma unroll
            for (int t = 0; t < 10; t++) {
                int idx = tid + t * 128;
                int d = idx >> 4, kc = (idx & 15) * 4;
                int bytes = min(max(kn - kc, 0), 4) * 4;
                int scol = (kc < kn) ? (kt + kc) : kt;
                cp16z(sV + (uint32_t)(d * VT_STR + kc) * 4u,
                      g_Vt + (size_t)(h * HD + d) * SEQ + scol, bytes);
            }
            asm volatile("cp.async.commit_group;\n");

            // S = Q K^T
            float sacc[8][4];
#pragma unroll
            for (int nt = 0; nt < 8; nt++)
#pragma unroll
                for (int r = 0; r < 4; r++) sacc[nt][r] = 0.f;

#pragma unroll
            for (int ksp = 0; ksp < 10; ksp++) {
                const int k0 = ksp * 8;
                uint32_t af[4], bf[8][2];
                af[0] = __float_as_uint(Qs[(m0 + g) * QS_STR + k0 + tg]);
                af[1] = __float_as_uint(Qs[(m0 + 8 + g) * QS_STR + k0 + tg]);
                af[2] = __float_as_uint(Qs[(m0 + g) * QS_STR + k0 + tg + 4]);
                af[3] = __float_as_uint(Qs[(m0 + 8 + g) * QS_STR + k0 + tg + 4]);
#pragma unroll
                for (int nt = 0; nt < 8; nt++) {
                    bf[nt][0] = __float_as_uint(Ks[(nt * 8 + g) * QS_STR + k0 + tg]);
                    bf[nt][1] = __float_as_uint(Ks[(nt * 8 + g) * QS_STR + k0 + tg + 4]);
                }
#pragma unroll
                for (int nt = 0; nt < 8; nt++)
                    mma_tf32(sacc[nt], af, bf[nt]);
            }

            __syncthreads();   // all warps done reading Ks

            // Issue K_{kt+64} (overlaps softmax + PV)
            if (kt + 64 < ke) {
                int knn = min(64, ke - (kt + 64));
#pragma unroll
                for (int t = 0; t < 10; t++) {
                    int idx = tid + t * 128;
                    int r = idx / 20, dc = (idx % 20) * 4;
                    int srow = (r < knn) ? (kt + 64 + r) : (kt + 64 - 1);
                    cp16z(sK + (uint32_t)(r * QS_STR + dc) * 4u,
                          g_K + (size_t)srow * DIM + h * HD + dc, (r < knn) ? 16 : 0);
                }
            }
            asm volatile("cp.async.commit_group;\n");

            if (kn < 64) {
#pragma unroll
                for (int nt = 0; nt < 8; nt++) {
                    int c = nt * 8 + 2 * tg;
                    if (c >= kn)     { sacc[nt][0] = -1e30f; sacc[nt][2] = -1e30f; }
                    if (c + 1 >= kn) { sacc[nt][1] = -1e30f; sacc[nt][3] = -1e30f; }
                }
            }

            // Online softmax
#pragma unroll
            for (int half = 0; half < 2; half++) {
                const int b = half * 2;
                float mloc = -1e30f;
#pragma unroll
                for (int nt = 0; nt < 8; nt++)
                    mloc = fmaxf(mloc, fmaxf(sacc[nt][b], sacc[nt][b + 1]));
                mloc = fmaxf(mloc, __shfl_xor_sync(0xffffffffu, mloc, 1));
                mloc = fmaxf(mloc, __shfl_xor_sync(0xffffffffu, mloc, 2));
                float mn = fmaxf(mrow[half], mloc);
                float fac = __expf(mrow[half] - mn);
                mrow[half] = mn;
                float rs = 0.f;
#pragma unroll
                for (int nt = 0; nt < 8; nt++) {
                    float p0 = __expf(sacc[nt][b] - mn);
                    float p1 = __expf(sacc[nt][b + 1] - mn);
                    sacc[nt][b] = p0; sacc[nt][b + 1] = p1;
                    rs += p0 + p1;
                }
                rs += __shfl_xor_sync(0xffffffffu, rs, 1);
                rs += __shfl_xor_sync(0xffffffffu, rs, 2);
                lrow[half] = lrow[half] * fac + rs;
#pragma unroll
                for (int nt = 0; nt < 10; nt++) { o[nt][b] *= fac; o[nt][b + 1] *= fac; }
            }

            // Stage P (tf32) — warp-private rows
#pragma unroll
            for (int nt = 0; nt < 8; nt++) {
                int c = nt * 8 + 2 * tg;
                Ps[(m0 + g) * VT_STR + c]         = f2tf32(sacc[nt][0]);
                Ps[(m0 + g) * VT_STR + c + 1]     = f2tf32(sacc[nt][1]);
                Ps[(m0 + 8 + g) * VT_STR + c]     = f2tf32(sacc[nt][2]);
                Ps[(m0 + 8 + g) * VT_STR + c + 1] = f2tf32(sacc[nt][3]);
            }

            // Wait V (newest group = K_{kt+64} may still be in flight)
            asm volatile("cp.async.wait_group 1;\n");
            __syncthreads();

            // O += P V
#pragma unroll
            for (int ksp = 0; ksp < 8; ksp++) {
                const int k0 = ksp * 8;
                uint32_t af[4], bf[10][2];
                af[0] = __float_as_uint(Ps[(m0 + g) * VT_STR + k0 + tg]);
                af[1] = __float_as_uint(Ps[(m0 + 8 + g) * VT_STR + k0 + tg]);
                af[2] = __float_as_uint(Ps[(m0 + g) * VT_STR + k0 + tg + 4]);
                af[3] = __float_as_uint(Ps[(m0 + 8 + g) * VT_STR + k0 + tg + 4]);
#pragma unroll
                for (int nt = 0; nt < 10; nt++) {
                    bf[nt][0] = __float_as_uint(Vt[(nt * 8 + g) * VT_STR + k0 + tg]);
                    bf[nt][1] = __float_as_uint(Vt[(nt * 8 + g) * VT_STR + k0 + tg + 4]);
                }
#pragma unroll
                for (int nt = 0; nt < 10; nt++)
                    mma_tf32(o[nt], af, bf[nt]);
            }
        }

        const float inv0 = 1.f / lrow[0];
        const float inv1 = 1.f / lrow[1];
#pragma unroll
        for (int nt = 0; nt < 10; nt++) {
            int c = h * HD + nt * 8 + 2 * tg;
            *(float2*)(out + (size_t)(qb + m0 + g) * DIM + c) =
                make_float2(f2tf32(o[nt][0] * inv0), f2tf32(o[nt][1] * inv0));
            *(float2*)(out + (size_t)(qb + m0 + 8 + g) * DIM + c) =
                make_float2(f2tf32(o[nt][2] * inv1), f2tf32(o[nt][3] * inv1));
        }
    }
}

// ---------------------------------------------------------------------------
extern "C" void kernel_launch(void* const* d_in, const int* in_sizes, int n_in,
                              void* d_out, int out_size)
{
    const float* X  = (const float*)d_in[0];
    const float* Wq = (const float*)d_in[1];
    const float* bq = (const float*)d_in[2];
    const float* Wk = (const float*)d_in[3];
    const float* bk = (const float*)d_in[4];
    const float* Wv = (const float*)d_in[5];
    const float* bv = (const float*)d_in[6];
    const float* Wo = (const float*)d_in[7];
    const float* bo = (const float*)d_in[8];
    const float* cs = (const float*)d_in[9];
    const float* sn = (const float*)d_in[10];
    const int*   cu = (const int*)d_in[11];
    float* out = (float*)d_out;

    void *pQ, *pK, *pVt, *pA, *pXr, *pWq, *pWk, *pWv, *pWo;
    cudaGetSymbolAddress(&pQ, g_Q);
    cudaGetSymbolAddress(&pK, g_K);
    cudaGetSymbolAddress(&pVt, g_Vt);
    cudaGetSymbolAddress(&pA, g_A);
    cudaGetSymbolAddress(&pXr, g_Xr);
    cudaGetSymbolAddress(&pWq, g_Wqr);
    cudaGetSymbolAddress(&pWk, g_Wkr);
    cudaGetSymbolAddress(&pWv, g_Wvr);
    cudaGetSymbolAddress(&pWo, g_Wor);

    cudaFuncSetAttribute(gemm_tf32_pipe<false>,
                         cudaFuncAttributeMaxDynamicSharedMemorySize, GEMM_SMEM);
    cudaFuncSetAttribute(gemm_tf32_pipe<true>,
                         cudaFuncAttributeMaxDynamicSharedMemorySize, GEMM_SMEM);
    cudaFuncSetAttribute(attn_mma,
                         cudaFuncAttributeMaxDynamicSharedMemorySize, ATTN_SMEM);

    const int ntot = NX4 + 4 * NW4;
    dim3 gg(DIM / BN, SEQ / BM);       // (8, 16) = 128 CTAs
    dim3 gb(512);

    cvt_all<<<(ntot + 255) / 256, 256>>>(X, Wq, Wk, Wv, Wo);

    gemm_tf32_pipe<false><<<gg, gb, GEMM_SMEM>>>((const float*)pXr, (const float*)pWq, bq, (float*)pQ, SEQ, DIM, DIM);
    gemm_tf32_pipe<false><<<gg, gb, GEMM_SMEM>>>((const float*)pXr, (const float*)pWk, bk, (float*)pK, SEQ, DIM, DIM);
    gemm_tf32_pipe<true ><<<gg, gb, GEMM_SMEM>>>((const float*)pXr, (const float*)pWv, bv, (float*)pVt, SEQ, DIM, DIM);

    int rope_total = SEQ * NH * (HD / 2);
    rope_kernel<<<(rope_total + 255) / 256, 256>>>(cs, sn);

    attn_mma<<<ATT_GRID, 128, ATTN_SMEM>>>(cu, (float*)pA);

    gemm_tf32_pipe<false><<<gg, gb, GEMM_SMEM>>>((const float*)pA, (const float*)pWo, bo, out, SEQ, DIM, DIM);
}

// round 11
// speedup vs baseline: 1.0546x; 1.0546x over previous
#include <cuda_runtime.h>
#include <math.h>
#include <stdint.h>

#define SEQ 2048
#define DIM 1280
#define NH  16
#define HD  80

// Scratch (device globals)
__device__ float g_Q[SEQ * DIM];
__device__ float g_K[SEQ * DIM];
__device__ float g_Vt[SEQ * DIM];    // V transposed: [DIM][SEQ], tf32-rounded
__device__ float g_A[SEQ * DIM];
__device__ float g_Xr[SEQ * DIM];    // tf32-rounded hidden_states
__device__ float g_Wqr[DIM * DIM];
__device__ float g_Wkr[DIM * DIM];
__device__ float g_Wvr[DIM * DIM];
__device__ float g_Wor[DIM * DIM];

__device__ __forceinline__ float f2tf32(float x) {
    uint32_t u;
    asm("cvt.rna.tf32.f32 %0, %1;" : "=r"(u) : "f"(x));
    return __uint_as_float(u);
}

__device__ __forceinline__ void mma_tf32(float* c, const uint32_t* a, const uint32_t* b) {
    asm("mma.sync.aligned.m16n8k8.row.col.f32.tf32.tf32.f32 "
        "{%0,%1,%2,%3}, {%4,%5,%6,%7}, {%8,%9}, {%0,%1,%2,%3};"
        : "+f"(c[0]), "+f"(c[1]), "+f"(c[2]), "+f"(c[3])
        : "r"(a[0]), "r"(a[1]), "r"(a[2]), "r"(a[3]), "r"(b[0]), "r"(b[1]));
}

__device__ __forceinline__ void cp16(uint32_t dst, const void* src) {
    asm volatile("cp.async.cg.shared.global [%0], [%1], 16;\n" :: "r"(dst), "l"(src));
}
__device__ __forceinline__ void cp16z(uint32_t dst, const void* src, int bytes) {
    asm volatile("cp.async.cg.shared.global [%0], [%1], 16, %2;\n"
                 :: "r"(dst), "l"(src), "r"(bytes));
}

// ---------------------------------------------------------------------------
// Fused tf32 rounding for X + all 4 weights (one launch).
// ---------------------------------------------------------------------------
#define NX4 (SEQ * DIM / 4)
#define NW4 (DIM * DIM / 4)
__global__ void cvt_all(const float* __restrict__ X,
                        const float* __restrict__ Wq, const float* __restrict__ Wk,
                        const float* __restrict__ Wv, const float* __restrict__ Wo)
{
    int i = blockIdx.x * blockDim.x + threadIdx.x;
    const float* src; float* dst; int off;
    if (i < NX4)               { src = X;  dst = g_Xr;  off = i; }
    else if (i < NX4 + NW4)    { src = Wq; dst = g_Wqr; off = i - NX4; }
    else if (i < NX4 + 2*NW4)  { src = Wk; dst = g_Wkr; off = i - NX4 - NW4; }
    else if (i < NX4 + 3*NW4)  { src = Wv; dst = g_Wvr; off = i - NX4 - 2*NW4; }
    else if (i < NX4 + 4*NW4)  { src = Wo; dst = g_Wor; off = i - NX4 - 3*NW4; }
    else return;
    float4 v = ((const float4*)src)[off];
    ((float4*)dst)[off] = make_float4(f2tf32(v.x), f2tf32(v.y), f2tf32(v.z), f2tf32(v.w));
}

// ---------------------------------------------------------------------------
// TF32 GEMM (NT), 2-stage cp.async pipeline (R5-proven sync structure:
// issue -> wait -> sync -> compute -> sync) + register fragment double-buffer
// in the compute phase (load ks+1 fragments while mma'ing ks).
// BM=128, BN=160 -> grid (8,16) = 128 CTAs. 256 thr = 8 warps (2x4),
// warp tile 64x40, acc[4][5][4].
// ---------------------------------------------------------------------------
#define BM 128
#define BN 160
#define BK 32
#define SST 36
#define GEMM_SMEM ((2 * BM * SST + 2 * BN * SST) * 4)   // 82944 B

template<bool TRANS>
__global__ __launch_bounds__(256, 1)
void gemm_tf32_pipe(const float* __restrict__ A, const float* __restrict__ B,
                    const float* __restrict__ bias, float* __restrict__ C,
                    int M, int N, int K)
{
    extern __shared__ float sm[];
    float* As = sm;                    // [2][BM*SST]
    float* Bs = sm + 2 * BM * SST;     // [2][BN*SST]

    const int tid = threadIdx.x;
    const int m0 = blockIdx.y * BM;
    const int n0 = blockIdx.x * BN;

    const int warp = tid >> 5, lane = tid & 31;
    const int wm = warp >> 2, wn = warp & 3;      // 2 x 4 warps
    const int g = lane >> 2, tg = lane & 3;

    const uint32_t sA = (uint32_t)__cvta_generic_to_shared(As);
    const uint32_t sB = (uint32_t)__cvta_generic_to_shared(Bs);

    float acc[4][5][4];
#pragma unroll
    for (int mt = 0; mt < 4; mt++)
#pragma unroll
        for (int nt = 0; nt < 5; nt++)
#pragma unroll
            for (int r = 0; r < 4; r++) acc[mt][nt][r] = 0.f;

    const int T = K / BK;   // 40

    auto issue = [&](int stage, int kt) {
#pragma unroll
        for (int t = 0; t < 4; t++) {             // A: 128 rows x 32 k
            int idx = tid + t * 256;
            int r = idx >> 3;
            int kc = (idx & 7) << 2;
            uint32_t off = (uint32_t)(stage * BM * SST + r * SST + kc) * 4u;
            cp16(sA + off, A + (size_t)(m0 + r) * K + kt + kc);
        }
#pragma unroll
        for (int t = 0; t < 5; t++) {             // B: 160 rows x 32 k
            int idx = tid + t * 256;
            int r = idx >> 3;
            int kc = (idx & 7) << 2;
            uint32_t off = (uint32_t)(stage * BN * SST + r * SST + kc) * 4u;
            cp16(sB + off, B + (size_t)(n0 + r) * K + kt + kc);
        }
        asm volatile("cp.async.commit_group;\n");
    };

    auto loadA = [&](const float* Asr, int k0, uint32_t af[4][4]) {
#pragma unroll
        for (int mt = 0; mt < 4; mt++) {
            int r = wm * 64 + mt * 16 + g;
            af[mt][0] = __float_as_uint(Asr[r * SST + k0 + tg]);
            af[mt][1] = __float_as_uint(Asr[(r + 8) * SST + k0 + tg]);
            af[mt][2] = __float_as_uint(Asr[r * SST + k0 + tg + 4]);
            af[mt][3] = __float_as_uint(Asr[(r + 8) * SST + k0 + tg + 4]);
        }
    };
    auto loadB = [&](const float* Bsr, int k0, uint32_t bf[5][2]) {
#pragma unroll
        for (int nt = 0; nt < 5; nt++) {
            int c = wn * 40 + nt * 8 + g;
            bf[nt][0] = __float_as_uint(Bsr[c * SST + k0 + tg]);
            bf[nt][1] = __float_as_uint(Bsr[c * SST + k0 + tg + 4]);
        }
    };

    issue(0, 0);

    for (int ti = 0; ti < T; ti++) {
        if (ti + 1 < T) {
            issue((ti + 1) & 1, (ti + 1) * BK);
            asm volatile("cp.async.wait_group 1;\n");
        } else {
            asm volatile("cp.async.wait_group 0;\n");
        }
        __syncthreads();                   // R5-proven: sync AFTER wait

        const float* Asr = As + (ti & 1) * BM * SST;
        const float* Bsr = Bs + (ti & 1) * BN * SST;

        // Fragment double-buffer: load ks+1 while mma'ing ks.
        uint32_t afa[4][4], bfa[5][2], afb[4][4], bfb[5][2];
        loadA(Asr, 0, afa);
        loadB(Bsr, 0, bfa);
#pragma unroll
        for (int ks = 0; ks < 4; ks++) {
            uint32_t (*afc)[4] = (ks & 1) ? afb : afa;
            uint32_t (*bfc)[2] = (ks & 1) ? bfb : bfa;
            uint32_t (*afn)[4] = (ks & 1) ? afa : afb;
            uint32_t (*bfn)[2] = (ks & 1) ? bfa : bfb;
            if (ks < 3) {
                loadA(Asr, (ks + 1) * 8, afn);
                loadB(Bsr, (ks + 1) * 8, bfn);
            }
#pragma unroll
            for (int mt = 0; mt < 4; mt++)
#pragma unroll
                for (int nt = 0; nt < 5; nt++)
                    mma_tf32(acc[mt][nt], afc[mt], bfc[nt]);
        }
        __syncthreads();                   // protect stage reuse next iter
    }

#pragma unroll
    for (int mt = 0; mt < 4; mt++) {
#pragma unroll
        for (int nt = 0; nt < 5; nt++) {
            int r = m0 + wm * 64 + mt * 16 + g;
            int c = n0 + wn * 40 + nt * 8 + 2 * tg;
            float2 bb = *(const float2*)(bias + c);
            if (!TRANS) {
                float2 v0 = make_float2(acc[mt][nt][0] + bb.x, acc[mt][nt][1] + bb.y);
                float2 v1 = make_float2(acc[mt][nt][2] + bb.x, acc[mt][nt][3] + bb.y);
                *(float2*)(C + (size_t)r * N + c) = v0;
                *(float2*)(C + (size_t)(r + 8) * N + c) = v1;
            } else {
                C[(size_t)c * M + r]           = f2tf32(acc[mt][nt][0] + bb.x);
                C[(size_t)(c + 1) * M + r]     = f2tf32(acc[mt][nt][1] + bb.y);
                C[(size_t)c * M + r + 8]       = f2tf32(acc[mt][nt][2] + bb.x);
                C[(size_t)(c + 1) * M + r + 8] = f2tf32(acc[mt][nt][3] + bb.y);
            }
        }
    }
}

// ---------------------------------------------------------------------------
// RoPE in place on g_Q / g_K. Q additionally pre-scaled by 1/sqrt(hd).
// Both outputs tf32-rounded so attention fills are pure copies.
// ---------------------------------------------------------------------------
__global__ void rope_kernel(const float* __restrict__ cs, const float* __restrict__ sn)
{
    int idx = blockIdx.x * blockDim.x + threadIdx.x;
    const int total = SEQ * NH * (HD / 2);
    if (idx >= total) return;
    int j = idx % (HD / 2);
    int h = (idx / (HD / 2)) % NH;
    int s = idx / ((HD / 2) * NH);
    int base = s * DIM + h * HD;
    const float scale = rsqrtf((float)HD);
    float c0 = cs[s * HD + j],      s0 = sn[s * HD + j];
    float c1 = cs[s * HD + j + 40], s1 = sn[s * HD + j + 40];
    {
        float x0 = g_Q[base + j], x1 = g_Q[base + j + 40];
        g_Q[base + j]      = f2tf32((x0 * c0 - x1 * s0) * scale);
        g_Q[base + j + 40] = f2tf32((x1 * c1 + x0 * s1) * scale);
    }
    {
        float x0 = g_K[base + j], x1 = g_K[base + j + 40];
        g_K[base + j]      = f2tf32(x0 * c0 - x1 * s0);
        g_K[base + j + 40] = f2tf32(x1 * c1 + x0 * s1);
    }
}

// ---------------------------------------------------------------------------
// Persistent segmented flash attention, tf32 mma, cp.async-pipelined fills.
// grid = 296 (148 SM x occ 2), 128 thr. (Unchanged R5 core — 305us baseline.)
// ---------------------------------------------------------------------------
#define ATT_GRID 296
#define QS_STR 84
#define VT_STR 68
#define AT_KS  (64 * QS_STR)
#define AT_VT  (2 * 64 * QS_STR)
#define AT_PS  (AT_VT + 80 * VT_STR)
#define ATTN_SMEM ((AT_PS + 64 * VT_STR) * 4)   // 82176 B

__global__ __launch_bounds__(128)
void attn_mma(const int* __restrict__ cu, float* __restrict__ out)
{
    extern __shared__ float sm[];
    float* Qs = sm;
    float* Ks = sm + AT_KS;
    float* Vt = sm + AT_VT;
    float* Ps = sm + AT_PS;

    const uint32_t sQ = (uint32_t)__cvta_generic_to_shared(Qs);
    const uint32_t sK = (uint32_t)__cvta_generic_to_shared(Ks);
    const uint32_t sV = (uint32_t)__cvta_generic_to_shared(Vt);

    const int tid = threadIdx.x;
    const int warp = tid >> 5, lane = tid & 31;
    const int g = lane >> 2, tg = lane & 3;
    const int m0 = warp * 16;

    for (int item = blockIdx.x; item < (SEQ / 64) * NH; item += ATT_GRID) {
        const int qb = (item >> 4) * 64;
        const int h  = item & 15;

        int ks = 0, ke = SEQ;
#pragma unroll
        for (int i = 0; i < 4; i++)
            if (qb >= cu[i] && qb < cu[i + 1]) { ks = cu[i]; ke = cu[i + 1]; }

        __syncthreads();

#pragma unroll
        for (int t = 0; t < 10; t++) {
            int idx = tid + t * 128;
            int r = idx / 20, dc = (idx % 20) * 4;
            cp16(sQ + (uint32_t)(r * QS_STR + dc) * 4u,
                 g_Q + (size_t)(qb + r) * DIM + h * HD + dc);
        }
        asm volatile("cp.async.commit_group;\n");
        {
            int kn0 = min(64, ke - ks);
#pragma unroll
            for (int t = 0; t < 10; t++) {
                int idx = tid + t * 128;
                int r = idx / 20, dc = (idx % 20) * 4;
                int srow = (r < kn0) ? (ks + r) : ks;
                cp16z(sK + (uint32_t)(r * QS_STR + dc) * 4u,
                      g_K + (size_t)srow * DIM + h * HD + dc, (r < kn0) ? 16 : 0);
            }
            asm volatile("cp.async.commit_group;\n");
        }

        float mrow[2] = {-1e30f, -1e30f};
        float lrow[2] = {0.f, 0.f};
        float o[10][4];
#pragma unroll
        for (int nt = 0; nt < 10; nt++)
#pragma unroll
            for (int r = 0; r < 4; r++) o[nt][r] = 0.f;

        for (int kt = ks; kt < ke; kt += 64) {
            int kn = min(64, ke - kt);
            asm volatile("cp.async.wait_group 0;\n");
            __syncthreads();

#pragma unroll
            for (int t = 0; t < 10; t++) {
                int idx = tid + t * 128;
                int d = idx >> 4, kc = (idx & 15) * 4;
                int bytes = min(max(kn - kc, 0), 4) * 4;
                int scol = (kc < kn) ? (kt + kc) : kt;
                cp16z(sV + (uint32_t)(d * VT_STR + kc) * 4u,
                      g_Vt + (size_t)(h * HD + d) * SEQ + scol, bytes);
            }
            asm volatile("cp.async.commit_group;\n");

            float sacc[8][4];
#pragma unroll
            for (int nt = 0; nt < 8; nt++)
#pragma unroll
                for (int r = 0; r < 4; r++) sacc[nt][r] = 0.f;

#pragma unroll
            for (int ksp = 0; ksp < 10; ksp++) {
                const int k0 = ksp * 8;
                uint32_t af[4], bf[8][2];
                af[0] = __float_as_uint(Qs[(m0 + g) * QS_STR + k0 + tg]);
                af[1] = __float_as_uint(Qs[(m0 + 8 + g) * QS_STR + k0 + tg]);
                af[2] = __float_as_uint(Qs[(m0 + g) * QS_STR + k0 + tg + 4]);
                af[3] = __float_as_uint(Qs[(m0 + 8 + g) * QS_STR + k0 + tg + 4]);
#pragma unroll
                for (int nt = 0; nt < 8; nt++) {
                    bf[nt][0] = __float_as_uint(Ks[(nt * 8 + g) * QS_STR + k0 + tg]);
                    bf[nt][1] = __float_as_uint(Ks[(nt * 8 + g) * QS_STR + k0 + tg + 4]);
                }
#pragma unroll
                for (int nt = 0; nt < 8; nt++)
                    mma_tf32(sacc[nt], af, bf[nt]);
            }

            __syncthreads();

            if (kt + 64 < ke) {
                int knn = min(64, ke - (kt + 64));
#pragma unroll
                for (int t = 0; t < 10; t++) {
                    int idx = tid + t * 128;
                    int r = idx / 20, dc = (idx % 20) * 4;
                    int srow = (r < knn) ? (kt + 64 + r) : (kt + 64 - 1);
                    cp16z(sK + (uint32_t)(r * QS_STR + dc) * 4u,
                          g_K + (size_t)srow * DIM + h * HD + dc, (r < knn) ? 16 : 0);
                }
            }
            asm volatile("cp.async.commit_group;\n");

            if (kn < 64) {
#pragma unroll
                for (int nt = 0; nt < 8; nt++) {
                    int c = nt * 8 + 2 * tg;
                    if (c >= kn)     { sacc[nt][0] = -1e30f; sacc[nt][2] = -1e30f; }
                    if (c + 1 >= kn) { sacc[nt][1] = -1e30f; sacc[nt][3] = -1e30f; }
                }
            }

#pragma unroll
            for (int half = 0; half < 2; half++) {
                const int b = half * 2;
                float mloc = -1e30f;
#pragma unroll
                for (int nt = 0; nt < 8; nt++)
                    mloc = fmaxf(mloc, fmaxf(sacc[nt][b], sacc[nt][b + 1]));
                mloc = fmaxf(mloc, __shfl_xor_sync(0xffffffffu, mloc, 1));
                mloc = fmaxf(mloc, __shfl_xor_sync(0xffffffffu, mloc, 2));
                float mn = fmaxf(mrow[half], mloc);
                float fac = __expf(mrow[half] - mn);
                mrow[half] = mn;
                float rs = 0.f;
#pragma unroll
                for (int nt = 0; nt < 8; nt++) {
                    float p0 = __expf(sacc[nt][b] - mn);
                    float p1 = __expf(sacc[nt][b + 1] - mn);
                    sacc[nt][b] = p0; sacc[nt][b + 1] = p1;
                    rs += p0 + p1;
                }
                rs += __shfl_xor_sync(0xffffffffu, rs, 1);
                rs += __shfl_xor_sync(0xffffffffu, rs, 2);
                lrow[half] = lrow[half] * fac + rs;
#pragma unroll
                for (int nt = 0; nt < 10; nt++) { o[nt][b] *= fac; o[nt][b + 1] *= fac; }
            }

#pragma unroll
            for (int nt = 0; nt < 8; nt++) {
                int c = nt * 8 + 2 * tg;
                Ps[(m0 + g) * VT_STR + c]         = f2tf32(sacc[nt][0]);
                Ps[(m0 + g) * VT_STR + c + 1]     = f2tf32(sacc[nt][1]);
                Ps[(m0 + 8 + g) * VT_STR + c]     = f2tf32(sacc[nt][2]);
                Ps[(m0 + 8 + g) * VT_STR + c + 1] = f2tf32(sacc[nt][3]);
            }

            asm volatile("cp.async.wait_group 1;\n");
            __syncthreads();

#pragma unroll
            for (int ksp = 0; ksp < 8; ksp++) {
                const int k0 = ksp * 8;
                uint32_t af[4], bf[10][2];
                af[0] = __float_as_uint(Ps[(m0 + g) * VT_STR + k0 + tg]);
                af[1] = __float_as_uint(Ps[(m0 + 8 + g) * VT_STR + k0 + tg]);
                af[2] = __float_as_uint(Ps[(m0 + g) * VT_STR + k0 + tg + 4]);
                af[3] = __float_as_uint(Ps[(m0 + 8 + g) * VT_STR + k0 + tg + 4]);
#pragma unroll
                for (int nt = 0; nt < 10; nt++) {
                    bf[nt][0] = __float_as_uint(Vt[(nt * 8 + g) * VT_STR + k0 + tg]);
                    bf[nt][1] = __float_as_uint(Vt[(nt * 8 + g) * VT_STR + k0 + tg + 4]);
                }
#pragma unroll
                for (int nt = 0; nt < 10; nt++)
                    mma_tf32(o[nt], af, bf[nt]);
            }
        }

        const float inv0 = 1.f / lrow[0];
        const float inv1 = 1.f / lrow[1];
#pragma unroll
        for (int nt = 0; nt < 10; nt++) {
            int c = h * HD + nt * 8 + 2 * tg;
            *(float2*)(out + (size_t)(qb + m0 + g) * DIM + c) =
                make_float2(f2tf32(o[nt][0] * inv0), f2tf32(o[nt][1] * inv0));
            *(float2*)(out + (size_t)(qb + m0 + 8 + g) * DIM + c) =
                make_float2(f2tf32(o[nt][2] * inv1), f2tf32(o[nt][3] * inv1));
        }
    }
}

// ---------------------------------------------------------------------------
extern "C" void kernel_launch(void* const* d_in, const int* in_sizes, int n_in,
                              void* d_out, int out_size)
{
    const float* X  = (const float*)d_in[0];
    const float* Wq = (const float*)d_in[1];
    const float* bq = (const float*)d_in[2];
    const float* Wk = (const float*)d_in[3];
    const float* bk = (const float*)d_in[4];
    const float* Wv = (const float*)d_in[5];
    const float* bv = (const float*)d_in[6];
    const float* Wo = (const float*)d_in[7];
    const float* bo = (const float*)d_in[8];
    const float* cs = (const float*)d_in[9];
    const float* sn = (const float*)d_in[10];
    const int*   cu = (const int*)d_in[11];
    float* out = (float*)d_out;

    void *pQ, *pK, *pVt, *pA, *pXr, *pWq, *pWk, *pWv, *pWo;
    cudaGetSymbolAddress(&pQ, g_Q);
    cudaGetSymbolAddress(&pK, g_K);
    cudaGetSymbolAddress(&pVt, g_Vt);
    cudaGetSymbolAddress(&pA, g_A);
    cudaGetSymbolAddress(&pXr, g_Xr);
    cudaGetSymbolAddress(&pWq, g_Wqr);
    cudaGetSymbolAddress(&pWk, g_Wkr);
    cudaGetSymbolAddress(&pWv, g_Wvr);
    cudaGetSymbolAddress(&pWo, g_Wor);

    cudaFuncSetAttribute(gemm_tf32_pipe<false>,
                         cudaFuncAttributeMaxDynamicSharedMemorySize, GEMM_SMEM);
    cudaFuncSetAttribute(gemm_tf32_pipe<true>,
                         cudaFuncAttributeMaxDynamicSharedMemorySize, GEMM_SMEM);
    cudaFuncSetAttribute(attn_mma,
                         cudaFuncAttributeMaxDynamicSharedMemorySize, ATTN_SMEM);

    const int ntot = NX4 + 4 * NW4;
    dim3 gg(DIM / BN, SEQ / BM);       // (8, 16) = 128 CTAs
    dim3 gb(256);

    cvt_all<<<(ntot + 255) / 256, 256>>>(X, Wq, Wk, Wv, Wo);

    gemm_tf32_pipe<false><<<gg, gb, GEMM_SMEM>>>((const float*)pXr, (const float*)pWq, bq, (float*)pQ, SEQ, DIM, DIM);
    gemm_tf32_pipe<false><<<gg, gb, GEMM_SMEM>>>((const float*)pXr, (const float*)pWk, bk, (float*)pK, SEQ, DIM, DIM);
    gemm_tf32_pipe<true ><<<gg, gb, GEMM_SMEM>>>((const float*)pXr, (const float*)pWv, bv, (float*)pVt, SEQ, DIM, DIM);

    int rope_total = SEQ * NH * (HD / 2);
    rope_kernel<<<(rope_total + 255) / 256, 256>>>(cs, sn);

    attn_mma<<<ATT_GRID, 128, ATTN_SMEM>>>(cu, (float*)pA);

    gemm_tf32_pipe<false><<<gg, gb, GEMM_SMEM>>>((const float*)pA, (const float*)pWo, bo, out, SEQ, DIM, DIM);
}

// round 12
// speedup vs baseline: 1.0740x; 1.0184x over previous
#include <cuda_runtime.h>
#include <math.h>
#include <stdint.h>

#define SEQ 2048
#define DIM 1280
#define NH  16
#define HD  80
#define DIMP 1296   // padded weight-row count (9 uniform 144-col tiles)

// Scratch (device globals)
__device__ float g_Q[SEQ * DIM];
__device__ float g_K[SEQ * DIM];
__device__ float g_Vt[SEQ * DIM];    // V transposed: [DIM][SEQ], tf32-rounded
__device__ float g_A[SEQ * DIM];
__device__ float g_Xr[SEQ * DIM];    // tf32-rounded hidden_states
__device__ float g_Wqr[DIMP * DIM];  // tf32-rounded weights, padded to 1296 rows
__device__ float g_Wkr[DIMP * DIM];
__device__ float g_Wvr[DIMP * DIM];
__device__ float g_Wor[DIMP * DIM];

__device__ __forceinline__ float f2tf32(float x) {
    uint32_t u;
    asm("cvt.rna.tf32.f32 %0, %1;" : "=r"(u) : "f"(x));
    return __uint_as_float(u);
}

__device__ __forceinline__ void mma_tf32(float* c, const uint32_t* a, const uint32_t* b) {
    asm("mma.sync.aligned.m16n8k8.row.col.f32.tf32.tf32.f32 "
        "{%0,%1,%2,%3}, {%4,%5,%6,%7}, {%8,%9}, {%0,%1,%2,%3};"
        : "+f"(c[0]), "+f"(c[1]), "+f"(c[2]), "+f"(c[3])
        : "r"(a[0]), "r"(a[1]), "r"(a[2]), "r"(a[3]), "r"(b[0]), "r"(b[1]));
}

__device__ __forceinline__ void cp16(uint32_t dst, const void* src) {
    asm volatile("cp.async.cg.shared.global [%0], [%1], 16;\n" :: "r"(dst), "l"(src));
}
__device__ __forceinline__ void cp16z(uint32_t dst, const void* src, int bytes) {
    asm volatile("cp.async.cg.shared.global [%0], [%1], 16, %2;\n"
                 :: "r"(dst), "l"(src), "r"(bytes));
}

// ---------------------------------------------------------------------------
// Fused tf32 rounding: X (2048x1280) + 4 weights padded to 1296x1280
// (pad rows written as zeros so every column tile is uniform width 144).
// ---------------------------------------------------------------------------
#define NX4  (SEQ * DIM / 4)
#define NW4  (DIM * DIM / 4)
#define NWP4 (DIMP * DIM / 4)
__global__ void cvt_all(const float* __restrict__ X,
                        const float* __restrict__ Wq, const float* __restrict__ Wk,
                        const float* __restrict__ Wv, const float* __restrict__ Wo)
{
    int i = blockIdx.x * blockDim.x + threadIdx.x;
    const float* src; float* dst; int off;
    if (i < NX4)                { src = X;  dst = g_Xr;  off = i; }
    else if (i < NX4 + NWP4)    { src = Wq; dst = g_Wqr; off = i - NX4; }
    else if (i < NX4 + 2*NWP4)  { src = Wk; dst = g_Wkr; off = i - NX4 - NWP4; }
    else if (i < NX4 + 3*NWP4)  { src = Wv; dst = g_Wvr; off = i - NX4 - 2*NWP4; }
    else if (i < NX4 + 4*NWP4)  { src = Wo; dst = g_Wor; off = i - NX4 - 3*NWP4; }
    else return;
    bool isw = (i >= NX4);
    if (isw && off >= NW4) {                       // weight pad rows -> zero
        ((float4*)dst)[off] = make_float4(0.f, 0.f, 0.f, 0.f);
        return;
    }
    float4 v = ((const float4*)src)[off];
    ((float4*)dst)[off] = make_float4(f2tf32(v.x), f2tf32(v.y), f2tf32(v.z), f2tf32(v.w));
}

// ---------------------------------------------------------------------------
// TF32 GEMM (NT), 2-stage cp.async pipeline, BALANCED 144-CTA grid.
// C[M,N] = A[M,K] B[N,K]^T + bias.  TRANS: store C transposed [N][M] (tf32).
// BM=128, BN=144 -> grid (9,16) = 144 CTAs on 148 SMs. 256 thr = 8 warps
// (4m x 2n), warp tile 32x72, acc[2][9][4]. B rows padded (1296) so all
// tiles uniform; epilogue guards col < N. Per-element K-order identical
// to the R5/R11 kernel -> bit-identical results.
// ---------------------------------------------------------------------------
#define BM 128
#define BN 144
#define BK 32
#define SST 36
#define GEMM_SMEM ((2 * BM * SST + 2 * BN * SST) * 4)   // 78336 B

template<bool TRANS>
__global__ __launch_bounds__(256, 1)
void gemm_tf32_pipe(const float* __restrict__ A, const float* __restrict__ B,
                    const float* __restrict__ bias, float* __restrict__ C,
                    int M, int N, int K)
{
    extern __shared__ float sm[];
    float* As = sm;                    // [2][BM*SST]
    float* Bs = sm + 2 * BM * SST;     // [2][BN*SST]

    const int tid = threadIdx.x;
    const int m0 = blockIdx.y * BM;
    const int n0 = blockIdx.x * BN;

    const int warp = tid >> 5, lane = tid & 31;
    const int wm = warp >> 1, wn = warp & 1;      // 4m x 2n warps
    const int g = lane >> 2, tg = lane & 3;

    const uint32_t sA = (uint32_t)__cvta_generic_to_shared(As);
    const uint32_t sB = (uint32_t)__cvta_generic_to_shared(Bs);

    float acc[2][9][4];
#pragma unroll
    for (int mt = 0; mt < 2; mt++)
#pragma unroll
        for (int nt = 0; nt < 9; nt++)
#pragma unroll
            for (int r = 0; r < 4; r++) acc[mt][nt][r] = 0.f;

    const int T = K / BK;   // 40

    auto issue = [&](int stage, int kt) {
#pragma unroll
        for (int t = 0; t < 4; t++) {             // A: 128 rows x 32 k = 1024 chunks
            int idx = tid + t * 256;
            int r = idx >> 3;
            int kc = (idx & 7) << 2;
            uint32_t off = (uint32_t)(stage * BM * SST + r * SST + kc) * 4u;
            cp16(sA + off, A + (size_t)(m0 + r) * K + kt + kc);
        }
#pragma unroll
        for (int t = 0; t < 4; t++) {             // B: 144 rows x 32 k = 1152 chunks
            int idx = tid + t * 256;
            int r = idx >> 3;
            int kc = (idx & 7) << 2;
            uint32_t off = (uint32_t)(stage * BN * SST + r * SST + kc) * 4u;
            cp16(sB + off, B + (size_t)(n0 + r) * K + kt + kc);
        }
        if (tid < 128) {
            int idx = tid + 1024;
            int r = idx >> 3;
            int kc = (idx & 7) << 2;
            uint32_t off = (uint32_t)(stage * BN * SST + r * SST + kc) * 4u;
            cp16(sB + off, B + (size_t)(n0 + r) * K + kt + kc);
        }
        asm volatile("cp.async.commit_group;\n");
    };

    auto loadA = [&](const float* Asr, int k0, uint32_t af[2][4]) {
#pragma unroll
        for (int mt = 0; mt < 2; mt++) {
            int r = wm * 32 + mt * 16 + g;
            af[mt][0] = __float_as_uint(Asr[r * SST + k0 + tg]);
            af[mt][1] = __float_as_uint(Asr[(r + 8) * SST + k0 + tg]);
            af[mt][2] = __float_as_uint(Asr[r * SST + k0 + tg + 4]);
            af[mt][3] = __float_as_uint(Asr[(r + 8) * SST + k0 + tg + 4]);
        }
    };
    auto loadB = [&](const float* Bsr, int k0, uint32_t bf[9][2]) {
#pragma unroll
        for (int nt = 0; nt < 9; nt++) {
            int c = wn * 72 + nt * 8 + g;
            bf[nt][0] = __float_as_uint(Bsr[c * SST + k0 + tg]);
            bf[nt][1] = __float_as_uint(Bsr[c * SST + k0 + tg + 4]);
        }
    };

    issue(0, 0);

    for (int ti = 0; ti < T; ti++) {
        if (ti + 1 < T) {
            issue((ti + 1) & 1, (ti + 1) * BK);
            asm volatile("cp.async.wait_group 1;\n");
        } else {
            asm volatile("cp.async.wait_group 0;\n");
        }
        __syncthreads();

        const float* Asr = As + (ti & 1) * BM * SST;
        const float* Bsr = Bs + (ti & 1) * BN * SST;

        uint32_t afa[2][4], bfa[9][2], afb[2][4], bfb[9][2];
        loadA(Asr, 0, afa);
        loadB(Bsr, 0, bfa);
#pragma unroll
        for (int ks = 0; ks < 4; ks++) {
            uint32_t (*afc)[4] = (ks & 1) ? afb : afa;
            uint32_t (*bfc)[2] = (ks & 1) ? bfb : bfa;
            uint32_t (*afn)[4] = (ks & 1) ? afa : afb;
            uint32_t (*bfn)[2] = (ks & 1) ? bfa : bfb;
            if (ks < 3) {
                loadA(Asr, (ks + 1) * 8, afn);
                loadB(Bsr, (ks + 1) * 8, bfn);
            }
#pragma unroll
            for (int mt = 0; mt < 2; mt++)
#pragma unroll
                for (int nt = 0; nt < 9; nt++)
                    mma_tf32(acc[mt][nt], afc[mt], bfc[nt]);
        }
        __syncthreads();
    }

    // Epilogue with column guards (tiles may overhang N=1280).
#pragma unroll
    for (int mt = 0; mt < 2; mt++) {
#pragma unroll
        for (int nt = 0; nt < 9; nt++) {
            int r = m0 + wm * 32 + mt * 16 + g;
            int c = n0 + wn * 72 + nt * 8 + 2 * tg;
            float b0 = (c < N)     ? bias[c]     : 0.f;
            float b1 = (c + 1 < N) ? bias[c + 1] : 0.f;
            if (!TRANS) {
                if (c < N) {
                    C[(size_t)r * N + c]       = acc[mt][nt][0] + b0;
                    C[(size_t)(r + 8) * N + c] = acc[mt][nt][2] + b0;
                }
                if (c + 1 < N) {
                    C[(size_t)r * N + c + 1]       = acc[mt][nt][1] + b1;
                    C[(size_t)(r + 8) * N + c + 1] = acc[mt][nt][3] + b1;
                }
            } else {
                if (c < N) {
                    C[(size_t)c * M + r]     = f2tf32(acc[mt][nt][0] + b0);
                    C[(size_t)c * M + r + 8] = f2tf32(acc[mt][nt][2] + b0);
                }
                if (c + 1 < N) {
                    C[(size_t)(c + 1) * M + r]     = f2tf32(acc[mt][nt][1] + b1);
                    C[(size_t)(c + 1) * M + r + 8] = f2tf32(acc[mt][nt][3] + b1);
                }
            }
        }
    }
}

// ---------------------------------------------------------------------------
// RoPE in place on g_Q / g_K, float4-vectorized (j handled 4 at a time).
// Q pre-scaled by 1/sqrt(hd); outputs tf32-rounded.
// ---------------------------------------------------------------------------
__global__ void rope_kernel(const float* __restrict__ cs, const float* __restrict__ sn)
{
    int idx = blockIdx.x * blockDim.x + threadIdx.x;
    const int total = SEQ * NH * 10;              // 10 float4 per (s,h) half-row
    if (idx >= total) return;
    int j4 = (idx % 10) * 4;
    int h = (idx / 10) % NH;
    int s = idx / (10 * NH);
    int base = s * DIM + h * HD;
    const float scale = rsqrtf((float)HD);

    float4 c0 = *(const float4*)(cs + s * HD + j4);
    float4 c1 = *(const float4*)(cs + s * HD + j4 + 40);
    float4 s0 = *(const float4*)(sn + s * HD + j4);
    float4 s1 = *(const float4*)(sn + s * HD + j4 + 40);

    {
        float4 x0 = *(const float4*)(g_Q + base + j4);
        float4 x1 = *(const float4*)(g_Q + base + j4 + 40);
        float4 o0, o1;
        o0.x = f2tf32((x0.x * c0.x - x1.x * s0.x) * scale);
        o0.y = f2tf32((x0.y * c0.y - x1.y * s0.y) * scale);
        o0.z = f2tf32((x0.z * c0.z - x1.z * s0.z) * scale);
        o0.w = f2tf32((x0.w * c0.w - x1.w * s0.w) * scale);
        o1.x = f2tf32((x1.x * c1.x + x0.x * s1.x) * scale);
        o1.y = f2tf32((x1.y * c1.y + x0.y * s1.y) * scale);
        o1.z = f2tf32((x1.z * c1.z + x0.z * s1.z) * scale);
        o1.w = f2tf32((x1.w * c1.w + x0.w * s1.w) * scale);
        *(float4*)(g_Q + base + j4)      = o0;
        *(float4*)(g_Q + base + j4 + 40) = o1;
    }
    {
        float4 x0 = *(const float4*)(g_K + base + j4);
        float4 x1 = *(const float4*)(g_K + base + j4 + 40);
        float4 o0, o1;
        o0.x = f2tf32(x0.x * c0.x - x1.x * s0.x);
        o0.y = f2tf32(x0.y * c0.y - x1.y * s0.y);
        o0.z = f2tf32(x0.z * c0.z - x1.z * s0.z);
        o0.w = f2tf32(x0.w * c0.w - x1.w * s0.w);
        o1.x = f2tf32(x1.x * c1.x + x0.x * s1.x);
        o1.y = f2tf32(x1.y * c1.y + x0.y * s1.y);
        o1.z = f2tf32(x1.z * c1.z + x0.z * s1.z);
        o1.w = f2tf32(x1.w * c1.w + x0.w * s1.w);
        *(float4*)(g_K + base + j4)      = o0;
        *(float4*)(g_K + base + j4 + 40) = o1;
    }
}

// ---------------------------------------------------------------------------
// Persistent segmented flash attention, tf32 mma, cp.async-pipelined fills.
// grid = 296 (148 SM x occ 2), 128 thr. (Unchanged — proven core.)
// ---------------------------------------------------------------------------
#define ATT_GRID 296
#define QS_STR 84
#define VT_STR 68
#define AT_KS  (64 * QS_STR)
#define AT_VT  (2 * 64 * QS_STR)
#define AT_PS  (AT_VT + 80 * VT_STR)
#define ATTN_SMEM ((AT_PS + 64 * VT_STR) * 4)   // 82176 B

__global__ __launch_bounds__(128)
void attn_mma(const int* __restrict__ cu, float* __restrict__ out)
{
    extern __shared__ float sm[];
    float* Qs = sm;
    float* Ks = sm + AT_KS;
    float* Vt = sm + AT_VT;
    float* Ps = sm + AT_PS;

    const uint32_t sQ = (uint32_t)__cvta_generic_to_shared(Qs);
    const uint32_t sK = (uint32_t)__cvta_generic_to_shared(Ks);
    const uint32_t sV = (uint32_t)__cvta_generic_to_shared(Vt);

    const int tid = threadIdx.x;
    const int warp = tid >> 5, lane = tid & 31;
    const int g = lane >> 2, tg = lane & 3;
    const int m0 = warp * 16;

    for (int item = blockIdx.x; item < (SEQ / 64) * NH; item += ATT_GRID) {
        const int qb = (item >> 4) * 64;
        const int h  = item & 15;

        int ks = 0, ke = SEQ;
#pragma unroll
        for (int i = 0; i < 4; i++)
            if (qb >= cu[i] && qb < cu[i + 1]) { ks = cu[i]; ke = cu[i + 1]; }

        __syncthreads();

#pragma unroll
        for (int t = 0; t < 10; t++) {
            int idx = tid + t * 128;
            int r = idx / 20, dc = (idx % 20) * 4;
            cp16(sQ + (uint32_t)(r * QS_STR + dc) * 4u,
                 g_Q + (size_t)(qb + r) * DIM + h * HD + dc);
        }
        asm volatile("cp.async.commit_group;\n");
        {
            int kn0 = min(64, ke - ks);
#pragma unroll
            for (int t = 0; t < 10; t++) {
                int idx = tid + t * 128;
                int r = idx / 20, dc = (idx % 20) * 4;
                int srow = (r < kn0) ? (ks + r) : ks;
                cp16z(sK + (uint32_t)(r * QS_STR + dc) * 4u,
                      g_K + (size_t)srow * DIM + h * HD + dc, (r < kn0) ? 16 : 0);
            }
            asm volatile("cp.async.commit_group;\n");
        }

        float mrow[2] = {-1e30f, -1e30f};
        float lrow[2] = {0.f, 0.f};
        float o[10][4];
#pragma unroll
        for (int nt = 0; nt < 10; nt++)
#pragma unroll
            for (int r = 0; r < 4; r++) o[nt][r] = 0.f;

        for (int kt = ks; kt < ke; kt += 64) {
            int kn = min(64, ke - kt);
            asm volatile("cp.async.wait_group 0;\n");
            __syncthreads();

#pragma unroll
            for (int t = 0; t < 10; t++) {
                int idx = tid + t * 128;
                int d = idx >> 4, kc = (idx & 15) * 4;
                int bytes = min(max(kn - kc, 0), 4) * 4;
                int scol = (kc < kn) ? (kt + kc) : kt;
                cp16z(sV + (uint32_t)(d * VT_STR + kc) * 4u,
                      g_Vt + (size_t)(h * HD + d) * SEQ + scol, bytes);
            }
            asm volatile("cp.async.commit_group;\n");

            float sacc[8][4];
#pragma unroll
            for (int nt = 0; nt < 8; nt++)
#pragma unroll
                for (int r = 0; r < 4; r++) sacc[nt][r] = 0.f;

#pragma unroll
            for (int ksp = 0; ksp < 10; ksp++) {
                const int k0 = ksp * 8;
                uint32_t af[4], bf[8][2];
                af[0] = __float_as_uint(Qs[(m0 + g) * QS_STR + k0 + tg]);
                af[1] = __float_as_uint(Qs[(m0 + 8 + g) * QS_STR + k0 + tg]);
                af[2] = __float_as_uint(Qs[(m0 + g) * QS_STR + k0 + tg + 4]);
                af[3] = __float_as_uint(Qs[(m0 + 8 + g) * QS_STR + k0 + tg + 4]);
#pragma unroll
                for (int nt = 0; nt < 8; nt++) {
                    bf[nt][0] = __float_as_uint(Ks[(nt * 8 + g) * QS_STR + k0 + tg]);
                    bf[nt][1] = __float_as_uint(Ks[(nt * 8 + g) * QS_STR + k0 + tg + 4]);
                }
#pragma unroll
                for (int nt = 0; nt < 8; nt++)
                    mma_tf32(sacc[nt], af, bf[nt]);
            }

            __syncthreads();

            if (kt + 64 < ke) {
                int knn = min(64, ke - (kt + 64));
#pragma unroll
                for (int t = 0; t < 10; t++) {
                    int idx = tid + t * 128;
                    int r = idx / 20, dc = (idx % 20) * 4;
                    int srow = (r < knn) ? (kt + 64 + r) : (kt + 64 - 1);
                    cp16z(sK + (uint32_t)(r * QS_STR + dc) * 4u,
                          g_K + (size_t)srow * DIM + h * HD + dc, (r < knn) ? 16 : 0);
                }
            }
            asm volatile("cp.async.commit_group;\n");

            if (kn < 64) {
#pragma unroll
                for (int nt = 0; nt < 8; nt++) {
                    int c = nt * 8 + 2 * tg;
                    if (c >= kn)     { sacc[nt][0] = -1e30f; sacc[nt][2] = -1e30f; }
                    if (c + 1 >= kn) { sacc[nt][1] = -1e30f; sacc[nt][3] = -1e30f; }
                }
            }

#pragma unroll
            for (int half = 0; half < 2; half++) {
                const int b = half * 2;
                float mloc = -1e30f;
#pragma unroll
                for (int nt = 0; nt < 8; nt++)
                    mloc = fmaxf(mloc, fmaxf(sacc[nt][b], sacc[nt][b + 1]));
                mloc = fmaxf(mloc, __shfl_xor_sync(0xffffffffu, mloc, 1));
                mloc = fmaxf(mloc, __shfl_xor_sync(0xffffffffu, mloc, 2));
                float mn = fmaxf(mrow[half], mloc);
                float fac = __expf(mrow[half] - mn);
                mrow[half] = mn;
                float rs = 0.f;
#pragma unroll
                for (int nt = 0; nt < 8; nt++) {
                    float p0 = __expf(sacc[nt][b] - mn);
                    float p1 = __expf(sacc[nt][b + 1] - mn);
                    sacc[nt][b] = p0; sacc[nt][b + 1] = p1;
                    rs += p0 + p1;
                }
                rs += __shfl_xor_sync(0xffffffffu, rs, 1);
                rs += __shfl_xor_sync(0xffffffffu, rs, 2);
                lrow[half] = lrow[half] * fac + rs;
#pragma unroll
                for (int nt = 0; nt < 10; nt++) { o[nt][b] *= fac; o[nt][b + 1] *= fac; }
            }

#pragma unroll
            for (int nt = 0; nt < 8; nt++) {
                int c = nt * 8 + 2 * tg;
                Ps[(m0 + g) * VT_STR + c]         = f2tf32(sacc[nt][0]);
                Ps[(m0 + g) * VT_STR + c + 1]     = f2tf32(sacc[nt][1]);
                Ps[(m0 + 8 + g) * VT_STR + c]     = f2tf32(sacc[nt][2]);
                Ps[(m0 + 8 + g) * VT_STR + c + 1] = f2tf32(sacc[nt][3]);
            }

            asm volatile("cp.async.wait_group 1;\n");
            __syncthreads();

#pragma unroll
            for (int ksp = 0; ksp < 8; ksp++) {
                const int k0 = ksp * 8;
                uint32_t af[4], bf[10][2];
                af[0] = __float_as_uint(Ps[(m0 + g) * VT_STR + k0 + tg]);
                af[1] = __float_as_uint(Ps[(m0 + 8 + g) * VT_STR + k0 + tg]);
                af[2] = __float_as_uint(Ps[(m0 + g) * VT_STR + k0 + tg + 4]);
                af[3] = __float_as_uint(Ps[(m0 + 8 + g) * VT_STR + k0 + tg + 4]);
#pragma unroll
                for (int nt = 0; nt < 10; nt++) {
                    bf[nt][0] = __float_as_uint(Vt[(nt * 8 + g) * VT_STR + k0 + tg]);
                    bf[nt][1] = __float_as_uint(Vt[(nt * 8 + g) * VT_STR + k0 + tg + 4]);
                }
#pragma unroll
                for (int nt = 0; nt < 10; nt++)
                    mma_tf32(o[nt], af, bf[nt]);
            }
        }

        const float inv0 = 1.f / lrow[0];
        const float inv1 = 1.f / lrow[1];
#pragma unroll
        for (int nt = 0; nt < 10; nt++) {
            int c = h * HD + nt * 8 + 2 * tg;
            *(float2*)(out + (size_t)(qb + m0 + g) * DIM + c) =
                make_float2(f2tf32(o[nt][0] * inv0), f2tf32(o[nt][1] * inv0));
            *(float2*)(out + (size_t)(qb + m0 + 8 + g) * DIM + c) =
                make_float2(f2tf32(o[nt][2] * inv1), f2tf32(o[nt][3] * inv1));
        }
    }
}

// ---------------------------------------------------------------------------
extern "C" void kernel_launch(void* const* d_in, const int* in_sizes, int n_in,
                              void* d_out, int out_size)
{
    const float* X  = (const float*)d_in[0];
    const float* Wq = (const float*)d_in[1];
    const float* bq = (const float*)d_in[2];
    const float* Wk = (const float*)d_in[3];
    const float* bk = (const float*)d_in[4];
    const float* Wv = (const float*)d_in[5];
    const float* bv = (const float*)d_in[6];
    const float* Wo = (const float*)d_in[7];
    const float* bo = (const float*)d_in[8];
    const float* cs = (const float*)d_in[9];
    const float* sn = (const float*)d_in[10];
    const int*   cu = (const int*)d_in[11];
    float* out = (float*)d_out;

    void *pQ, *pK, *pVt, *pA, *pXr, *pWq, *pWk, *pWv, *pWo;
    cudaGetSymbolAddress(&pQ, g_Q);
    cudaGetSymbolAddress(&pK, g_K);
    cudaGetSymbolAddress(&pVt, g_Vt);
    cudaGetSymbolAddress(&pA, g_A);
    cudaGetSymbolAddress(&pXr, g_Xr);
    cudaGetSymbolAddress(&pWq, g_Wqr);
    cudaGetSymbolAddress(&pWk, g_Wkr);
    cudaGetSymbolAddress(&pWv, g_Wvr);
    cudaGetSymbolAddress(&pWo, g_Wor);

    cudaFuncSetAttribute(gemm_tf32_pipe<false>,
                         cudaFuncAttributeMaxDynamicSharedMemorySize, GEMM_SMEM);
    cudaFuncSetAttribute(gemm_tf32_pipe<true>,
                         cudaFuncAttributeMaxDynamicSharedMemorySize, GEMM_SMEM);
    cudaFuncSetAttribute(attn_mma,
                         cudaFuncAttributeMaxDynamicSharedMemorySize, ATTN_SMEM);

    const int ntot = NX4 + 4 * NWP4;
    dim3 gg(DIMP / BN, SEQ / BM);      // (9, 16) = 144 CTAs
    dim3 gb(256);

    cvt_all<<<(ntot + 255) / 256, 256>>>(X, Wq, Wk, Wv, Wo);

    gemm_tf32_pipe<false><<<gg, gb, GEMM_SMEM>>>((const float*)pXr, (const float*)pWq, bq, (float*)pQ, SEQ, DIM, DIM);
    gemm_tf32_pipe<false><<<gg, gb, GEMM_SMEM>>>((const float*)pXr, (const float*)pWk, bk, (float*)pK, SEQ, DIM, DIM);
    gemm_tf32_pipe<true ><<<gg, gb, GEMM_SMEM>>>((const float*)pXr, (const float*)pWv, bv, (float*)pVt, SEQ, DIM, DIM);

    int rope_total = SEQ * NH * 10;
    rope_kernel<<<(rope_total + 255) / 256, 256>>>(cs, sn);

    attn_mma<<<ATT_GRID, 128, ATTN_SMEM>>>(cu, (float*)pA);

    gemm_tf32_pipe<false><<<gg, gb, GEMM_SMEM>>>((const float*)pA, (const float*)pWo, bo, out, SEQ, DIM, DIM);
}

// round 13
// speedup vs baseline: 1.2077x; 1.1245x over previous
#include <cuda_runtime.h>
#include <math.h>
#include <stdint.h>

#define SEQ 2048
#define DIM 1280
#define NH  16
#define HD  80
#define DIMP 1296            // padded weight rows (9 uniform 144-col tiles)
#define RBX (SEQ / 16)       // 128 row-blocks of 16
#define KBX (DIM / 8)        // 160 k-blocks of 8
#define CBW (DIMP / 8)       // 162 col-blocks of 8 (padded)

// Scratch (device globals)
__device__ float g_Q[SEQ * DIM];
__device__ float g_K[SEQ * DIM];
__device__ float g_Vt[SEQ * DIM];     // V transposed [DIM][SEQ], tf32-rounded
__device__ float g_Xap[SEQ * DIM];    // X in A-fragment order, tf32
__device__ float g_Aap[SEQ * DIM];    // attention out in A-fragment order, tf32
__device__ float g_Wqp[DIMP * DIM];   // weights in B-fragment order, tf32
__device__ float g_Wkp[DIMP * DIM];
__device__ float g_Wvp[DIMP * DIM];
__device__ float g_Wop[DIMP * DIM];

__device__ __forceinline__ float f2tf32(float x) {
    uint32_t u;
    asm("cvt.rna.tf32.f32 %0, %1;" : "=r"(u) : "f"(x));
    return __uint_as_float(u);
}

__device__ __forceinline__ void mma_tf32(float* c, const uint32_t* a, const uint32_t* b) {
    asm("mma.sync.aligned.m16n8k8.row.col.f32.tf32.tf32.f32 "
        "{%0,%1,%2,%3}, {%4,%5,%6,%7}, {%8,%9}, {%0,%1,%2,%3};"
        : "+f"(c[0]), "+f"(c[1]), "+f"(c[2]), "+f"(c[3])
        : "r"(a[0]), "r"(a[1]), "r"(a[2]), "r"(a[3]), "r"(b[0]), "r"(b[1]));
}

__device__ __forceinline__ void cp16(uint32_t dst, const void* src) {
    asm volatile("cp.async.cg.shared.global [%0], [%1], 16;\n" :: "r"(dst), "l"(src));
}
__device__ __forceinline__ void cp16z(uint32_t dst, const void* src, int bytes) {
    asm volatile("cp.async.cg.shared.global [%0], [%1], 16, %2;\n"
                 :: "r"(dst), "l"(src), "r"(bytes));
}

// ---------------------------------------------------------------------------
// permute_all: X -> A-fragment order (float4 per lane: a0,a1,a2,a3);
// 4 weights -> B-fragment order (float2 per lane: b0,b1). tf32-rounded.
// Fragment defs (m16n8k8 row.col): lane (g=l>>2, tg=l&3):
//   a0=A[g][tg] a1=A[g+8][tg] a2=A[g][tg+4] a3=A[g+8][tg+4]
//   b0=B[c=g][tg] b1=B[g][tg+4]
// ---------------------------------------------------------------------------
#define NXP (RBX * KBX * 32)     // 655360 float4 outputs
#define NWP (CBW * KBX * 32)     // 829440 float2 outputs per weight
__global__ void permute_all(const float* __restrict__ X,
                            const float* __restrict__ Wq, const float* __restrict__ Wk,
                            const float* __restrict__ Wv, const float* __restrict__ Wo)
{
    int i = blockIdx.x * blockDim.x + threadIdx.x;
    if (i < NXP) {
        int lane = i & 31, t = i >> 5;
        int kb = t % KBX, rb = t / KBX;
        int g = lane >> 2, tg = lane & 3;
        int r = rb * 16 + g, c = kb * 8 + tg;
        float4 v;
        v.x = f2tf32(X[(size_t)r * DIM + c]);
        v.y = f2tf32(X[(size_t)(r + 8) * DIM + c]);
        v.z = f2tf32(X[(size_t)r * DIM + c + 4]);
        v.w = f2tf32(X[(size_t)(r + 8) * DIM + c + 4]);
        ((float4*)g_Xap)[i] = v;
        return;
    }
    int j = i - NXP;
    int widx = j / NWP;
    if (widx >= 4) return;
    int k = j - widx * NWP;
    const float* W = (widx == 0) ? Wq : (widx == 1) ? Wk : (widx == 2) ? Wv : Wo;
    float* dst = (widx == 0) ? g_Wqp : (widx == 1) ? g_Wkp : (widx == 2) ? g_Wvp : g_Wop;
    int lane = k & 31, t = k >> 5;
    int kb = t % KBX, cb = t / KBX;
    int g = lane >> 2, tg = lane & 3;
    int r = cb * 8 + g, c = kb * 8 + tg;
    float2 v;
    if (r < DIM) {
        v.x = f2tf32(W[(size_t)r * DIM + c]);
        v.y = f2tf32(W[(size_t)r * DIM + c + 4]);
    } else {
        v = make_float2(0.f, 0.f);
    }
    ((float2*)dst)[k] = v;
}

// ---------------------------------------------------------------------------
// TF32 GEMM (NT) on fragment-order operands. BM=128, BN=144 -> 144 CTAs.
// 256 thr = 8 warps (4m x 2n), warp tile 32x72, acc[2][9][4].
// Per ks: 2x LDS.128 (A) + 9x LDS.64 (B) instead of 26x LDS.32.
// A block (rb,kb): 128 floats at (rb*KBX+kb)*128; B block (cb,kb): 64 floats.
// Same products / accumulation order as R12 -> bit-identical output.
// ---------------------------------------------------------------------------
#define BM 128
#define BN 144
#define BK 32
#define A_STAGE (8 * 4 * 128)     // 4096 floats
#define B_STAGE (18 * 4 * 64)     // 4608 floats
#define STAGEF (A_STAGE + B_STAGE)
#define GEMM_SMEM (2 * STAGEF * 4)  // 69632 B

template<bool TRANS>
__global__ __launch_bounds__(256, 1)
void gemm_tf32_frag(const float* __restrict__ Aap, const float* __restrict__ Bbp,
                    const float* __restrict__ bias, float* __restrict__ C,
                    int M, int N)
{
    extern __shared__ float sm[];
    const int tid = threadIdx.x;
    const int m0 = blockIdx.y * BM;
    const int n0 = blockIdx.x * BN;
    const int rb0 = m0 >> 4;              // row-block base
    const int cb0 = blockIdx.x * 18;      // col-block base

    const int warp = tid >> 5, lane = tid & 31;
    const int wm = warp >> 1, wn = warp & 1;   // 4m x 2n warps
    const int g = lane >> 2, tg = lane & 3;

    const uint32_t sbase = (uint32_t)__cvta_generic_to_shared(sm);

    float acc[2][9][4];
#pragma unroll
    for (int mt = 0; mt < 2; mt++)
#pragma unroll
        for (int nt = 0; nt < 9; nt++)
#pragma unroll
            for (int r = 0; r < 4; r++) acc[mt][nt][r] = 0.f;

    const int T = DIM / BK;   // 40

    auto issue = [&](int stage, int kt) {
        const int kb0 = kt >> 3;
        const uint32_t base = sbase + (uint32_t)stage * STAGEF * 4u;
#pragma unroll
        for (int t = 0; t < 4; t++) {          // A: 1024 16B-chunks
            int ci = tid + t * 256;
            int blk = ci >> 5;                 // 0..31 (rb_l*4 + kb_l)
            int rb_l = blk >> 2, kb_l = blk & 3;
            int l16 = ci & 31;
            cp16(base + (uint32_t)(blk * 128 + l16 * 4) * 4u,
                 Aap + ((size_t)(rb0 + rb_l) * KBX + kb0 + kb_l) * 128 + l16 * 4);
        }
#pragma unroll
        for (int t = 0; t < 5; t++) {          // B: 1152 16B-chunks
            int ci = tid + t * 256;
            if (ci < 1152) {
                int blk = ci >> 4;             // 0..71 (cb_l*4 + kb_l)
                int cb_l = blk >> 2, kb_l = blk & 3;
                int l16 = ci & 15;
                cp16(base + (uint32_t)(A_STAGE + blk * 64 + l16 * 4) * 4u,
                     Bbp + ((size_t)(cb0 + cb_l) * KBX + kb0 + kb_l) * 64 + l16 * 4);
            }
        }
        asm volatile("cp.async.commit_group;\n");
    };

    auto loadA = [&](const float* Asr, int ks, uint32_t af[2][4]) {
#pragma unroll
        for (int mt = 0; mt < 2; mt++) {
            float4 v = *(const float4*)(Asr + ((wm * 2 + mt) * 4 + ks) * 128 + lane * 4);
            af[mt][0] = __float_as_uint(v.x);
            af[mt][1] = __float_as_uint(v.y);
            af[mt][2] = __float_as_uint(v.z);
            af[mt][3] = __float_as_uint(v.w);
        }
    };
    auto loadB = [&](const float* Bsr, int ks, uint32_t bf[9][2]) {
#pragma unroll
        for (int nt = 0; nt < 9; nt++) {
            float2 v = *(const float2*)(Bsr + ((wn * 9 + nt) * 4 + ks) * 64 + lane * 2);
            bf[nt][0] = __float_as_uint(v.x);
            bf[nt][1] = __float_as_uint(v.y);
        }
    };

    issue(0, 0);

    for (int ti = 0; ti < T; ti++) {
        if (ti + 1 < T) {
            issue((ti + 1) & 1, (ti + 1) * BK);
            asm volatile("cp.async.wait_group 1;\n");
        } else {
            asm volatile("cp.async.wait_group 0;\n");
        }
        __syncthreads();

        const float* Asr = sm + (ti & 1) * STAGEF;
        const float* Bsr = Asr + A_STAGE;

        uint32_t afa[2][4], bfa[9][2], afb[2][4], bfb[9][2];
        loadA(Asr, 0, afa);
        loadB(Bsr, 0, bfa);
#pragma unroll
        for (int ks = 0; ks < 4; ks++) {
            uint32_t (*afc)[4] = (ks & 1) ? afb : afa;
            uint32_t (*bfc)[2] = (ks & 1) ? bfb : bfa;
            uint32_t (*afn)[4] = (ks & 1) ? afa : afb;
            uint32_t (*bfn)[2] = (ks & 1) ? bfa : bfb;
            if (ks < 3) {
                loadA(Asr, ks + 1, afn);
                loadB(Bsr, ks + 1, bfn);
            }
#pragma unroll
            for (int mt = 0; mt < 2; mt++)
#pragma unroll
                for (int nt = 0; nt < 9; nt++)
                    mma_tf32(acc[mt][nt], afc[mt], bfc[nt]);
        }
        __syncthreads();
    }

    // Epilogue with column guards (tiles may overhang N=1280).
#pragma unroll
    for (int mt = 0; mt < 2; mt++) {
#pragma unroll
        for (int nt = 0; nt < 9; nt++) {
            int r = m0 + wm * 32 + mt * 16 + g;
            int c = n0 + wn * 72 + nt * 8 + 2 * tg;
            float b0 = (c < N)     ? bias[c]     : 0.f;
            float b1 = (c + 1 < N) ? bias[c + 1] : 0.f;
            if (!TRANS) {
                if (c < N) {
                    C[(size_t)r * N + c]       = acc[mt][nt][0] + b0;
                    C[(size_t)(r + 8) * N + c] = acc[mt][nt][2] + b0;
                }
                if (c + 1 < N) {
                    C[(size_t)r * N + c + 1]       = acc[mt][nt][1] + b1;
                    C[(size_t)(r + 8) * N + c + 1] = acc[mt][nt][3] + b1;
                }
            } else {
                if (c < N) {
                    C[(size_t)c * M + r]     = f2tf32(acc[mt][nt][0] + b0);
                    C[(size_t)c * M + r + 8] = f2tf32(acc[mt][nt][2] + b0);
                }
                if (c + 1 < N) {
                    C[(size_t)(c + 1) * M + r]     = f2tf32(acc[mt][nt][1] + b1);
                    C[(size_t)(c + 1) * M + r + 8] = f2tf32(acc[mt][nt][3] + b1);
                }
            }
        }
    }
}

// ---------------------------------------------------------------------------
// RoPE in place on g_Q / g_K, float4-vectorized. Q pre-scaled; tf32-rounded.
// ---------------------------------------------------------------------------
__global__ void rope_kernel(const float* __restrict__ cs, const float* __restrict__ sn)
{
    int idx = blockIdx.x * blockDim.x + threadIdx.x;
    const int total = SEQ * NH * 10;
    if (idx >= total) return;
    int j4 = (idx % 10) * 4;
    int h = (idx / 10) % NH;
    int s = idx / (10 * NH);
    int base = s * DIM + h * HD;
    const float scale = rsqrtf((float)HD);

    float4 c0 = *(const float4*)(cs + s * HD + j4);
    float4 c1 = *(const float4*)(cs + s * HD + j4 + 40);
    float4 s0 = *(const float4*)(sn + s * HD + j4);
    float4 s1 = *(const float4*)(sn + s * HD + j4 + 40);

    {
        float4 x0 = *(const float4*)(g_Q + base + j4);
        float4 x1 = *(const float4*)(g_Q + base + j4 + 40);
        float4 o0, o1;
        o0.x = f2tf32((x0.x * c0.x - x1.x * s0.x) * scale);
        o0.y = f2tf32((x0.y * c0.y - x1.y * s0.y) * scale);
        o0.z = f2tf32((x0.z * c0.z - x1.z * s0.z) * scale);
        o0.w = f2tf32((x0.w * c0.w - x1.w * s0.w) * scale);
        o1.x = f2tf32((x1.x * c1.x + x0.x * s1.x) * scale);
        o1.y = f2tf32((x1.y * c1.y + x0.y * s1.y) * scale);
        o1.z = f2tf32((x1.z * c1.z + x0.z * s1.z) * scale);
        o1.w = f2tf32((x1.w * c1.w + x0.w * s1.w) * scale);
        *(float4*)(g_Q + base + j4)      = o0;
        *(float4*)(g_Q + base + j4 + 40) = o1;
    }
    {
        float4 x0 = *(const float4*)(g_K + base + j4);
        float4 x1 = *(const float4*)(g_K + base + j4 + 40);
        float4 o0, o1;
        o0.x = f2tf32(x0.x * c0.x - x1.x * s0.x);
        o0.y = f2tf32(x0.y * c0.y - x1.y * s0.y);
        o0.z = f2tf32(x0.z * c0.z - x1.z * s0.z);
        o0.w = f2tf32(x0.w * c0.w - x1.w * s0.w);
        o1.x = f2tf32(x1.x * c1.x + x0.x * s1.x);
        o1.y = f2tf32(x1.y * c1.y + x0.y * s1.y);
        o1.z = f2tf32(x1.z * c1.z + x0.z * s1.z);
        o1.w = f2tf32(x1.w * c1.w + x0.w * s1.w);
        *(float4*)(g_K + base + j4)      = o0;
        *(float4*)(g_K + base + j4 + 40) = o1;
    }
}

// ---------------------------------------------------------------------------
// Persistent segmented flash attention (proven core). Epilogue writes the
// output in A-fragment order to g_Aap via a warp-private bounce through Qs.
// ---------------------------------------------------------------------------
#define ATT_GRID 296
#define QS_STR 84
#define VT_STR 68
#define AT_KS  (64 * QS_STR)
#define AT_VT  (2 * 64 * QS_STR)
#define AT_PS  (AT_VT + 80 * VT_STR)
#define ATTN_SMEM ((AT_PS + 64 * VT_STR) * 4)   // 82176 B

__global__ __launch_bounds__(128)
void attn_mma(const int* __restrict__ cu)
{
    extern __shared__ float sm[];
    float* Qs = sm;
    float* Ks = sm + AT_KS;
    float* Vt = sm + AT_VT;
    float* Ps = sm + AT_PS;

    const uint32_t sQ = (uint32_t)__cvta_generic_to_shared(Qs);
    const uint32_t sK = (uint32_t)__cvta_generic_to_shared(Ks);
    const uint32_t sV = (uint32_t)__cvta_generic_to_shared(Vt);

    const int tid = threadIdx.x;
    const int warp = tid >> 5, lane = tid & 31;
    const int g = lane >> 2, tg = lane & 3;
    const int m0 = warp * 16;

    for (int item = blockIdx.x; item < (SEQ / 64) * NH; item += ATT_GRID) {
        const int qb = (item >> 4) * 64;
        const int h  = item & 15;

        int ks = 0, ke = SEQ;
#pragma unroll
        for (int i = 0; i < 4; i++)
            if (qb >= cu[i] && qb < cu[i + 1]) { ks = cu[i]; ke = cu[i + 1]; }

        __syncthreads();

#pragma unroll
        for (int t = 0; t < 10; t++) {
            int idx = tid + t * 128;
            int r = idx / 20, dc = (idx % 20) * 4;
            cp16(sQ + (uint32_t)(r * QS_STR + dc) * 4u,
                 g_Q + (size_t)(qb + r) * DIM + h * HD + dc);
        }
        asm volatile("cp.async.commit_group;\n");
        {
            int kn0 = min(64, ke - ks);
#pragma unroll
            for (int t = 0; t < 10; t++) {
                int idx = tid + t * 128;
                int r = idx / 20, dc = (idx % 20) * 4;
                int srow = (r < kn0) ? (ks + r) : ks;
                cp16z(sK + (uint32_t)(r * QS_STR + dc) * 4u,
                      g_K + (size_t)srow * DIM + h * HD + dc, (r < kn0) ? 16 : 0);
            }
            asm volatile("cp.async.commit_group;\n");
        }

        float mrow[2] = {-1e30f, -1e30f};
        float lrow[2] = {0.f, 0.f};
        float o[10][4];
#pragma unroll
        for (int nt = 0; nt < 10; nt++)
#pragma unroll
            for (int r = 0; r < 4; r++) o[nt][r] = 0.f;

        for (int kt = ks; kt < ke; kt += 64) {
            int kn = min(64, ke - kt);
            asm volatile("cp.async.wait_group 0;\n");
            __syncthreads();

#pragma unroll
            for (int t = 0; t < 10; t++) {
                int idx = tid + t * 128;
                int d = idx >> 4, kc = (idx & 15) * 4;
                int bytes = min(max(kn - kc, 0), 4) * 4;
                int scol = (kc < kn) ? (kt + kc) : kt;
                cp16z(sV + (uint32_t)(d * VT_STR + kc) * 4u,
                      g_Vt + (size_t)(h * HD + d) * SEQ + scol, bytes);
            }
            asm volatile("cp.async.commit_group;\n");

            float sacc[8][4];
#pragma unroll
            for (int nt = 0; nt < 8; nt++)
#pragma unroll
                for (int r = 0; r < 4; r++) sacc[nt][r] = 0.f;

#pragma unroll
            for (int ksp = 0; ksp < 10; ksp++) {
                const int k0 = ksp * 8;
                uint32_t af[4], bf[8][2];
                af[0] = __float_as_uint(Qs[(m0 + g) * QS_STR + k0 + tg]);
                af[1] = __float_as_uint(Qs[(m0 + 8 + g) * QS_STR + k0 + tg]);
                af[2] = __float_as_uint(Qs[(m0 + g) * QS_STR + k0 + tg + 4]);
                af[3] = __float_as_uint(Qs[(m0 + 8 + g) * QS_STR + k0 + tg + 4]);
#pragma unroll
                for (int nt = 0; nt < 8; nt++) {
                    bf[nt][0] = __float_as_uint(Ks[(nt * 8 + g) * QS_STR + k0 + tg]);
                    bf[nt][1] = __float_as_uint(Ks[(nt * 8 + g) * QS_STR + k0 + tg + 4]);
                }
#pragma unroll
                for (int nt = 0; nt < 8; nt++)
                    mma_tf32(sacc[nt], af, bf[nt]);
            }

            __syncthreads();

            if (kt + 64 < ke) {
                int knn = min(64, ke - (kt + 64));
#pragma unroll
                for (int t = 0; t < 10; t++) {
                    int idx = tid + t * 128;
                    int r = idx / 20, dc = (idx % 20) * 4;
                    int srow = (r < knn) ? (kt + 64 + r) : (kt + 64 - 1);
                    cp16z(sK + (uint32_t)(r * QS_STR + dc) * 4u,
                          g_K + (size_t)srow * DIM + h * HD + dc, (r < knn) ? 16 : 0);
                }
            }
            asm volatile("cp.async.commit_group;\n");

            if (kn < 64) {
#pragma unroll
                for (int nt = 0; nt < 8; nt++) {
                    int c = nt * 8 + 2 * tg;
                    if (c >= kn)     { sacc[nt][0] = -1e30f; sacc[nt][2] = -1e30f; }
                    if (c + 1 >= kn) { sacc[nt][1] = -1e30f; sacc[nt][3] = -1e30f; }
                }
            }

#pragma unroll
            for (int half = 0; half < 2; half++) {
                const int b = half * 2;
                float mloc = -1e30f;
#pragma unroll
                for (int nt = 0; nt < 8; nt++)
                    mloc = fmaxf(mloc, fmaxf(sacc[nt][b], sacc[nt][b + 1]));
                mloc = fmaxf(mloc, __shfl_xor_sync(0xffffffffu, mloc, 1));
                mloc = fmaxf(mloc, __shfl_xor_sync(0xffffffffu, mloc, 2));
                float mn = fmaxf(mrow[half], mloc);
                float fac = __expf(mrow[half] - mn);
                mrow[half] = mn;
                float rs = 0.f;
#pragma unroll
                for (int nt = 0; nt < 8; nt++) {
                    float p0 = __expf(sacc[nt][b] - mn);
                    float p1 = __expf(sacc[nt][b + 1] - mn);
                    sacc[nt][b] = p0; sacc[nt][b + 1] = p1;
                    rs += p0 + p1;
                }
                rs += __shfl_xor_sync(0xffffffffu, rs, 1);
                rs += __shfl_xor_sync(0xffffffffu, rs, 2);
                lrow[half] = lrow[half] * fac + rs;
#pragma unroll
                for (int nt = 0; nt < 10; nt++) { o[nt][b] *= fac; o[nt][b + 1] *= fac; }
            }

#pragma unroll
            for (int nt = 0; nt < 8; nt++) {
                int c = nt * 8 + 2 * tg;
                Ps[(m0 + g) * VT_STR + c]         = f2tf32(sacc[nt][0]);
                Ps[(m0 + g) * VT_STR + c + 1]     = f2tf32(sacc[nt][1]);
                Ps[(m0 + 8 + g) * VT_STR + c]     = f2tf32(sacc[nt][2]);
                Ps[(m0 + 8 + g) * VT_STR + c + 1] = f2tf32(sacc[nt][3]);
            }

            asm volatile("cp.async.wait_group 1;\n");
            __syncthreads();

#pragma unroll
            for (int ksp = 0; ksp < 8; ksp++) {
                const int k0 = ksp * 8;
                uint32_t af[4], bf[10][2];
                af[0] = __float_as_uint(Ps[(m0 + g) * VT_STR + k0 + tg]);
                af[1] = __float_as_uint(Ps[(m0 + 8 + g) * VT_STR + k0 + tg]);
                af[2] = __float_as_uint(Ps[(m0 + g) * VT_STR + k0 + tg + 4]);
                af[3] = __float_as_uint(Ps[(m0 + 8 + g) * VT_STR + k0 + tg + 4]);
#pragma unroll
                for (int nt = 0; nt < 10; nt++) {
                    bf[nt][0] = __float_as_uint(Vt[(nt * 8 + g) * VT_STR + k0 + tg]);
                    bf[nt][1] = __float_as_uint(Vt[(nt * 8 + g) * VT_STR + k0 + tg + 4]);
                }
#pragma unroll
                for (int nt = 0; nt < 10; nt++)
                    mma_tf32(o[nt], af, bf[nt]);
            }
        }

        // Epilogue: normalize, bounce through warp-private Qs rows, then write
        // A-fragment-order float4 to g_Aap (tf32-rounded).
        const float inv0 = 1.f / lrow[0];
        const float inv1 = 1.f / lrow[1];
#pragma unroll
        for (int nt = 0; nt < 10; nt++) {
            int c = nt * 8 + 2 * tg;
            Qs[(m0 + g) * QS_STR + c]         = o[nt][0] * inv0;
            Qs[(m0 + g) * QS_STR + c + 1]     = o[nt][1] * inv0;
            Qs[(m0 + 8 + g) * QS_STR + c]     = o[nt][2] * inv1;
            Qs[(m0 + 8 + g) * QS_STR + c + 1] = o[nt][3] * inv1;
        }
        __syncwarp();

        const int rb = (qb + m0) >> 4;
#pragma unroll
        for (int nt = 0; nt < 10; nt++) {
            int kb = h * 10 + nt;
            float4 v;
            v.x = f2tf32(Qs[(m0 + g) * QS_STR + nt * 8 + tg]);
            v.y = f2tf32(Qs[(m0 + 8 + g) * QS_STR + nt * 8 + tg]);
            v.z = f2tf32(Qs[(m0 + g) * QS_STR + nt * 8 + tg + 4]);
            v.w = f2tf32(Qs[(m0 + 8 + g) * QS_STR + nt * 8 + tg + 4]);
            ((float4*)g_Aap)[(size_t)(rb * KBX + kb) * 32 + lane] = v;
        }
        __syncwarp();
    }
}

// ---------------------------------------------------------------------------
extern "C" void kernel_launch(void* const* d_in, const int* in_sizes, int n_in,
                              void* d_out, int out_size)
{
    const float* X  = (const float*)d_in[0];
    const float* Wq = (const float*)d_in[1];
    const float* bq = (const float*)d_in[2];
    const float* Wk = (const float*)d_in[3];
    const float* bk = (const float*)d_in[4];
    const float* Wv = (const float*)d_in[5];
    const float* bv = (const float*)d_in[6];
    const float* Wo = (const float*)d_in[7];
    const float* bo = (const float*)d_in[8];
    const float* cs = (const float*)d_in[9];
    const float* sn = (const float*)d_in[10];
    const int*   cu = (const int*)d_in[11];
    float* out = (float*)d_out;

    void *pQ, *pK, *pVt, *pXap, *pAap, *pWq, *pWk, *pWv, *pWo;
    cudaGetSymbolAddress(&pQ, g_Q);
    cudaGetSymbolAddress(&pK, g_K);
    cudaGetSymbolAddress(&pVt, g_Vt);
    cudaGetSymbolAddress(&pXap, g_Xap);
    cudaGetSymbolAddress(&pAap, g_Aap);
    cudaGetSymbolAddress(&pWq, g_Wqp);
    cudaGetSymbolAddress(&pWk, g_Wkp);
    cudaGetSymbolAddress(&pWv, g_Wvp);
    cudaGetSymbolAddress(&pWo, g_Wop);

    cudaFuncSetAttribute(gemm_tf32_frag<false>,
                         cudaFuncAttributeMaxDynamicSharedMemorySize, GEMM_SMEM);
    cudaFuncSetAttribute(gemm_tf32_frag<true>,
                         cudaFuncAttributeMaxDynamicSharedMemorySize, GEMM_SMEM);
    cudaFuncSetAttribute(attn_mma,
                         cudaFuncAttributeMaxDynamicSharedMemorySize, ATTN_SMEM);

    const int ntot = NXP + 4 * NWP;
    dim3 gg(DIMP / BN, SEQ / BM);      // (9, 16) = 144 CTAs
    dim3 gb(256);

    permute_all<<<(ntot + 255) / 256, 256>>>(X, Wq, Wk, Wv, Wo);

    gemm_tf32_frag<false><<<gg, gb, GEMM_SMEM>>>((const float*)pXap, (const float*)pWq, bq, (float*)pQ, SEQ, DIM);
    gemm_tf32_frag<false><<<gg, gb, GEMM_SMEM>>>((const float*)pXap, (const float*)pWk, bk, (float*)pK, SEQ, DIM);
    gemm_tf32_frag<true ><<<gg, gb, GEMM_SMEM>>>((const float*)pXap, (const float*)pWv, bv, (float*)pVt, SEQ, DIM);

    int rope_total = SEQ * NH * 10;
    rope_kernel<<<(rope_total + 255) / 256, 256>>>(cs, sn);

    attn_mma<<<ATT_GRID, 128, ATTN_SMEM>>>(cu);

    gemm_tf32_frag<false><<<gg, gb, GEMM_SMEM>>>((const float*)pAap, (const float*)pWo, bo, out, SEQ, DIM);
}